// round 14
// baseline (speedup 1.0000x reference)
#include <cuda_runtime.h>
#include <math.h>

#define SS      50
#define NBATCH  64
#define EDIM    300
#define HDIM    512
#define G4      2048
#define ESDIM   1024
#define VTGT    10000
#define TDEC    49
#define NH      (NBATCH*HDIM)
#define NG4     (NBATCH*G4)
#define MOUT    (TDEC*NBATCH)
#define KBIG    1536
#define BSTRIDE 24
#define KP      304
#define KBIG2   912
#define KBIG3   3072

// ---------------- scratch (device globals; no runtime allocation) ----------------
__device__ float g_emb_src[SS*NBATCH*EDIM];
__device__ float g_demb  [TDEC*NBATCH*EDIM];
__device__ float g_xpf   [SS*NBATCH*G4];
__device__ float g_xpb   [SS*NBATCH*G4];
__device__ float g_dxp   [TDEC*NBATCH*G4];
__device__ float g_es    [SS*NBATCH*ESDIM];
__device__ float g_h_enc [2*2*NBATCH*HDIM];   // [parity][dir][n][h]
__device__ float g_c_enc [2*2*NBATCH*HDIM];
__device__ float g_hcat  [NBATCH*ESDIM];
__device__ float g_ccat  [NBATCH*ESDIM];
__device__ float g_dec_h [2*NBATCH*HDIM];
__device__ float g_dec_c [2*NBATCH*HDIM];
__device__ float g_esproj[SS*NBATCH];
__device__ float g_esw   [SS*NBATCH*G4];      // es[s,n,:]·Wih_ctx^T
__device__ float g_hhist [TDEC*NBATCH*HDIM];
__device__ float g_part  [8*NBATCH*G4];       // slots 0-3: K-partials, slot 4: ctx
__device__ float g_zb    [G4];
__device__ unsigned short g_abig[MOUT*KBIG];      // bf16 bits: [Ah|Ah|Al]
__device__ unsigned short g_bbig[VTGT*KBIG];      // bf16 bits: [Bh|Bl|Bh]
__device__ unsigned short g_ea2 [SS*NBATCH*KBIG2];
__device__ unsigned short g_da2 [TDEC*NBATCH*KBIG2];
__device__ unsigned short g_wf2 [G4*KBIG2];
__device__ unsigned short g_wb2 [G4*KBIG2];
__device__ unsigned short g_wd2 [G4*KBIG2];
__device__ unsigned short g_es3 [SS*NBATCH*KBIG3];
__device__ unsigned short g_wc3 [G4*KBIG3];

// ---------------- bf16 bit helpers (round-to-nearest-even) ----------------
__device__ __forceinline__ unsigned short f2bf(float x){
    unsigned int u = __float_as_uint(x);
    unsigned int r = (u + 0x7fffu + ((u >> 16) & 1u)) >> 16;
    return (unsigned short)r;
}
__device__ __forceinline__ float bf2f(unsigned short b){
    return __uint_as_float(((unsigned int)b) << 16);
}

// ---------------- small utility kernels ----------------
__global__ void zero_kernel(float* __restrict__ p, int n){
    int i = blockIdx.x*blockDim.x + threadIdx.x;
    if (i < n) p[i] = 0.f;
}

__global__ void embed_kernel(const int* __restrict__ tok,
                             const float* __restrict__ table,
                             float* __restrict__ out, int rows){
    int i = blockIdx.x*blockDim.x + threadIdx.x;
    int total = rows * EDIM;
    if (i >= total) return;
    int r = i / EDIM, e = i - r*EDIM;
    out[i] = table[(size_t)tok[r]*EDIM + e];
}

__global__ void hccat_kernel(){
    int i = blockIdx.x*blockDim.x + threadIdx.x;
    if (i >= NBATCH*ESDIM) return;
    int n = i >> 10, k = i & 1023;
    int src = (k < HDIM) ? (0*NH + n*HDIM + k)
                         : (1*NH + n*HDIM + (k - HDIM));
    g_hcat[i] = g_h_enc[src];
    g_ccat[i] = g_c_enc[src];
}

// Phase-D conversions (K=512 splits, KBIG=1536)
__global__ void convA_kernel(const float* __restrict__ X){
    int i = blockIdx.x*blockDim.x + threadIdx.x;
    if (i >= MOUT*HDIM) return;
    int m = i >> 9, k = i & 511;
    float x = X[i];
    unsigned short hi = f2bf(x);
    unsigned short lo = f2bf(x - bf2f(hi));
    g_abig[(size_t)m*KBIG + k]        = hi;
    g_abig[(size_t)m*KBIG + 512 + k]  = hi;
    g_abig[(size_t)m*KBIG + 1024 + k] = lo;
}

__global__ void convB_kernel(const float* __restrict__ W){
    int i = blockIdx.x*blockDim.x + threadIdx.x;
    if (i >= VTGT*HDIM) return;
    int n = i >> 9, k = i & 511;
    float x = W[i];
    unsigned short hi = f2bf(x);
    unsigned short lo = f2bf(x - bf2f(hi));
    g_bbig[(size_t)n*KBIG + k]        = hi;
    g_bbig[(size_t)n*KBIG + 512 + k]  = lo;
    g_bbig[(size_t)n*KBIG + 1024 + k] = hi;
}

// Phase-A conversions (K=300 padded to 304, KBIG2=912)
__global__ void convA2_kernel(const float* __restrict__ X,
                              unsigned short* __restrict__ dst, int rows){
    int i = blockIdx.x*blockDim.x + threadIdx.x;
    if (i >= rows*KP) return;
    int m = i / KP, k = i - m*KP;
    unsigned short hi = 0, lo = 0;
    if (k < EDIM){
        float x = X[(size_t)m*EDIM + k];
        hi = f2bf(x);
        lo = f2bf(x - bf2f(hi));
    }
    dst[(size_t)m*KBIG2 + k]        = hi;
    dst[(size_t)m*KBIG2 + KP + k]   = hi;
    dst[(size_t)m*KBIG2 + 2*KP + k] = lo;
}

__global__ void convW2_kernel(const float* __restrict__ W,
                              unsigned short* __restrict__ dst, int ldw, int koff){
    int i = blockIdx.x*blockDim.x + threadIdx.x;
    if (i >= G4*KP) return;
    int n = i / KP, k = i - n*KP;
    unsigned short hi = 0, lo = 0;
    if (k < EDIM){
        float x = W[(size_t)n*ldw + koff + k];
        hi = f2bf(x);
        lo = f2bf(x - bf2f(hi));
    }
    dst[(size_t)n*KBIG2 + k]        = hi;
    dst[(size_t)n*KBIG2 + KP + k]   = lo;
    dst[(size_t)n*KBIG2 + 2*KP + k] = hi;
}

// esW conversions (K=1024, KBIG3=3072)
__global__ void convES_kernel(){
    int i = blockIdx.x*blockDim.x + threadIdx.x;
    if (i >= SS*NBATCH*ESDIM) return;
    int m = i >> 10, k = i & 1023;
    float x = g_es[i];
    unsigned short hi = f2bf(x);
    unsigned short lo = f2bf(x - bf2f(hi));
    g_es3[(size_t)m*KBIG3 + k]        = hi;
    g_es3[(size_t)m*KBIG3 + 1024 + k] = hi;
    g_es3[(size_t)m*KBIG3 + 2048 + k] = lo;
}

__global__ void convW3_kernel(const float* __restrict__ W, int ldw){
    int i = blockIdx.x*blockDim.x + threadIdx.x;
    if (i >= G4*ESDIM) return;
    int n = i >> 10, k = i & 1023;
    float x = W[(size_t)n*ldw + k];
    unsigned short hi = f2bf(x);
    unsigned short lo = f2bf(x - bf2f(hi));
    g_wc3[(size_t)n*KBIG3 + k]        = hi;
    g_wc3[(size_t)n*KBIG3 + 1024 + k] = lo;
    g_wc3[(size_t)n*KBIG3 + 2048 + k] = hi;
}

// ---------------- small fp32 GEMM (bridge only): C[M,N] = A*B^T + bias ----------------
__global__ __launch_bounds__(256)
void gemm_kernel(const float* __restrict__ A, int lda,
                 const float* __restrict__ B, int ldb,
                 const float* __restrict__ bias,
                 float* __restrict__ C, int ldc,
                 int M, int N, int K)
{
    __shared__ float As[8][68];
    __shared__ float Bs[8][68];
    const int tid = threadIdx.x;
    const int tx = tid & 15, ty = tid >> 4;
    const int mb = blockIdx.y * 64, nb = blockIdx.x * 64;
    float acc[4][4] = {};

    for (int k0 = 0; k0 < K; k0 += 8) {
        #pragma unroll
        for (int i = 0; i < 2; i++) {
            int idx = tid + i*256;
            int kk = idx & 7, rr = idx >> 3;
            int m = mb + rr, k = k0 + kk;
            As[kk][rr] = (m < M && k < K) ? A[(size_t)m*lda + k] : 0.f;
            int nn = nb + rr;
            Bs[kk][rr] = (nn < N && k < K) ? B[(size_t)nn*ldb + k] : 0.f;
        }
        __syncthreads();
        #pragma unroll
        for (int kk = 0; kk < 8; kk++) {
            float a0 = As[kk][ty*4+0], a1 = As[kk][ty*4+1];
            float a2 = As[kk][ty*4+2], a3 = As[kk][ty*4+3];
            float b0 = Bs[kk][tx*4+0], b1 = Bs[kk][tx*4+1];
            float b2 = Bs[kk][tx*4+2], b3 = Bs[kk][tx*4+3];
            acc[0][0] += a0*b0; acc[0][1] += a0*b1; acc[0][2] += a0*b2; acc[0][3] += a0*b3;
            acc[1][0] += a1*b0; acc[1][1] += a1*b1; acc[1][2] += a1*b2; acc[1][3] += a1*b3;
            acc[2][0] += a2*b0; acc[2][1] += a2*b1; acc[2][2] += a2*b2; acc[2][3] += a2*b3;
            acc[3][0] += a3*b0; acc[3][1] += a3*b1; acc[3][2] += a3*b2; acc[3][3] += a3*b3;
        }
        __syncthreads();
    }
    #pragma unroll
    for (int i = 0; i < 4; i++) {
        int m = mb + ty*4 + i;
        if (m >= M) continue;
        #pragma unroll
        for (int j = 0; j < 4; j++) {
            int nn = nb + tx*4 + j;
            if (nn >= N) continue;
            C[(size_t)m*ldc + nn] = acc[i][j] + (bias ? bias[nn] : 0.f);
        }
    }
}

// ---------------- tensor-core bf16-split GEMM: C[M,N] = A'[M,K]*B'[N,K]^T + bias ----------------
__device__ __forceinline__ void ldsm_x4(unsigned int* r, unsigned int addr){
    asm volatile("ldmatrix.sync.aligned.m8n8.x4.shared.b16 {%0,%1,%2,%3}, [%4];"
        : "=r"(r[0]), "=r"(r[1]), "=r"(r[2]), "=r"(r[3]) : "r"(addr));
}
__device__ __forceinline__ void mma16816(float* c, const unsigned int* a, const unsigned int* b){
    asm volatile("mma.sync.aligned.m16n8k16.row.col.f32.bf16.bf16.f32 "
        "{%0,%1,%2,%3}, {%4,%5,%6,%7}, {%8,%9}, {%0,%1,%2,%3};"
        : "+f"(c[0]), "+f"(c[1]), "+f"(c[2]), "+f"(c[3])
        : "r"(a[0]), "r"(a[1]), "r"(a[2]), "r"(a[3]), "r"(b[0]), "r"(b[1]));
}

__global__ __launch_bounds__(256)
void gemm_tc_kernel(const unsigned short* __restrict__ A,
                    const unsigned short* __restrict__ B,
                    const float* __restrict__ bias,
                    float* __restrict__ C, int M, int N, int K)
{
    __shared__ __align__(16) unsigned short As[2*128*BSTRIDE];
    __shared__ __align__(16) unsigned short Bs[2*128*BSTRIDE];
    const int tid  = threadIdx.x;
    const int mb   = blockIdx.y * 128;
    const int nb   = blockIdx.x * 128;
    const int warp = tid >> 5;
    const int lane = tid & 31;
    const int wm   = warp & 1;       // 2x4 warp grid; warp tile 64x32
    const int wn   = warp >> 1;

    const int lrow = tid >> 1;       // 0..127
    const int lk8  = (tid & 1) * 8;  // 0 or 8 (shorts)

    float4 va = make_float4(0.f, 0.f, 0.f, 0.f);
    float4 vb = make_float4(0.f, 0.f, 0.f, 0.f);
    if (mb + lrow < M) va = *(const float4*)(A + (size_t)(mb + lrow)*K + lk8);
    if (nb + lrow < N) vb = *(const float4*)(B + (size_t)(nb + lrow)*K + lk8);
    *(float4*)&As[lrow*BSTRIDE + lk8] = va;
    *(float4*)&Bs[lrow*BSTRIDE + lk8] = vb;
    __syncthreads();

    float acc[4][4][4];
    #pragma unroll
    for (int i = 0; i < 4; i++)
        #pragma unroll
        for (int j = 0; j < 4; j++) {
            acc[i][j][0] = 0.f; acc[i][j][1] = 0.f;
            acc[i][j][2] = 0.f; acc[i][j][3] = 0.f;
        }

    const int fr  = (lane & 7) + ((lane >> 3) & 1) * 8;   // A: row within 16
    const int fcA = ((lane >> 4) & 1) * 8;                // A: k-half
    const int frB = (lane & 7) + ((lane >> 4) & 1) * 8;   // B: n row within 16
    const int fcB = ((lane >> 3) & 1) * 8;                // B: k-half

    const unsigned int a_base = (unsigned int)__cvta_generic_to_shared(&As[0]);
    const unsigned int b_base = (unsigned int)__cvta_generic_to_shared(&Bs[0]);
    const unsigned int stage_bytes = 128u * BSTRIDE * 2u;

    const int NT = K / 16;
    for (int t = 0; t < NT; t++) {
        const int buf = t & 1;
        if (t + 1 < NT) {
            const int k0 = (t + 1) * 16;
            va = make_float4(0.f, 0.f, 0.f, 0.f);
            vb = make_float4(0.f, 0.f, 0.f, 0.f);
            if (mb + lrow < M) va = *(const float4*)(A + (size_t)(mb + lrow)*K + k0 + lk8);
            if (nb + lrow < N) vb = *(const float4*)(B + (size_t)(nb + lrow)*K + k0 + lk8);
        }

        unsigned int areg[4][4];
        unsigned int breg[4][2];
        const unsigned int ab = a_base + (unsigned int)buf * stage_bytes;
        const unsigned int bb = b_base + (unsigned int)buf * stage_bytes;
        #pragma unroll
        for (int i = 0; i < 4; i++) {
            int row = wm*64 + i*16 + fr;
            ldsm_x4(areg[i], ab + (unsigned int)(row*BSTRIDE + fcA) * 2u);
        }
        #pragma unroll
        for (int p = 0; p < 2; p++) {
            int row = wn*32 + p*16 + frB;
            unsigned int r4[4];
            ldsm_x4(r4, bb + (unsigned int)(row*BSTRIDE + fcB) * 2u);
            breg[p*2][0]   = r4[0];
            breg[p*2][1]   = r4[1];
            breg[p*2+1][0] = r4[2];
            breg[p*2+1][1] = r4[3];
        }
        #pragma unroll
        for (int i = 0; i < 4; i++)
            #pragma unroll
            for (int j = 0; j < 4; j++)
                mma16816(acc[i][j], areg[i], breg[j]);

        if (t + 1 < NT) {
            int nbuf = buf ^ 1;
            *(float4*)&As[nbuf*128*BSTRIDE + lrow*BSTRIDE + lk8] = va;
            *(float4*)&Bs[nbuf*128*BSTRIDE + lrow*BSTRIDE + lk8] = vb;
        }
        __syncthreads();
    }

    const int er = lane >> 2;
    const int ec = (lane & 3) * 2;
    #pragma unroll
    for (int i = 0; i < 4; i++) {
        #pragma unroll
        for (int j = 0; j < 4; j++) {
            int m0 = mb + wm*64 + i*16 + er;
            int n0 = nb + wn*32 + j*8 + ec;
            if (n0 < N) {
                if (m0 < M) {
                    C[(size_t)m0*N + n0] = acc[i][j][0] + bias[n0];
                    if (n0+1 < N) C[(size_t)m0*N + n0+1] = acc[i][j][1] + bias[n0+1];
                }
                if (m0+8 < M) {
                    C[(size_t)(m0+8)*N + n0] = acc[i][j][2] + bias[n0];
                    if (n0+1 < N) C[(size_t)(m0+8)*N + n0+1] = acc[i][j][3] + bias[n0+1];
                }
            }
        }
    }
}

// ---------------- LSTM gate GEMM (split-K, dual input): partial[slot][n][2048] ----------------
__global__ __launch_bounds__(256)
void lstm_gemm_kernel(const float* __restrict__ A0, const float* __restrict__ A1, int lda,
                      const float* __restrict__ W0, const float* __restrict__ W1, int ldw,
                      int kchunk, float* __restrict__ part)
{
    __shared__ float hs[16][68];
    __shared__ float ws[16][68];
    const int tid = threadIdx.x;
    const int dir = blockIdx.z;
    const int slot = blockIdx.y * gridDim.z + blockIdx.z;
    const float* __restrict__ A = dir ? A1 : A0;
    const float* __restrict__ W = dir ? W1 : W0;
    const int kbeg = blockIdx.y * kchunk;
    const int j0 = blockIdx.x * 16;

    const int r  = tid >> 2;
    const int kq = tid & 3;
    const int wrow = (r >> 4) * HDIM + j0 + (r & 15);
    const int tx = tid & 15, ty = tid >> 4;

    const float* Aptr = A + (size_t)r * lda + kbeg + kq*4;
    const float* Wptr = W + (size_t)wrow * ldw + kbeg + kq*4;

    float4 fa = *(const float4*)Aptr;
    float4 fw = *(const float4*)Wptr;

    float acc[4][4] = {};
    const int ktiles = kchunk / 16;

    for (int t = 0; t < ktiles; t++) {
        hs[kq*4+0][r] = fa.x; hs[kq*4+1][r] = fa.y; hs[kq*4+2][r] = fa.z; hs[kq*4+3][r] = fa.w;
        ws[kq*4+0][r] = fw.x; ws[kq*4+1][r] = fw.y; ws[kq*4+2][r] = fw.z; ws[kq*4+3][r] = fw.w;
        __syncthreads();
        if (t + 1 < ktiles) {
            fa = *(const float4*)(Aptr + (t+1)*16);
            fw = *(const float4*)(Wptr + (t+1)*16);
        }
        #pragma unroll
        for (int kk = 0; kk < 16; kk++) {
            float4 av = *(const float4*)&hs[kk][ty*4];
            float4 bv = *(const float4*)&ws[kk][tx*4];
            acc[0][0] += av.x*bv.x; acc[0][1] += av.x*bv.y; acc[0][2] += av.x*bv.z; acc[0][3] += av.x*bv.w;
            acc[1][0] += av.y*bv.x; acc[1][1] += av.y*bv.y; acc[1][2] += av.y*bv.z; acc[1][3] += av.y*bv.w;
            acc[2][0] += av.z*bv.x; acc[2][1] += av.z*bv.y; acc[2][2] += av.z*bv.z; acc[2][3] += av.z*bv.w;
            acc[3][0] += av.w*bv.x; acc[3][1] += av.w*bv.y; acc[3][2] += av.w*bv.z; acc[3][3] += av.w*bv.w;
        }
        __syncthreads();
    }

    const int gate = tx >> 2;
    const int col0 = gate*HDIM + j0 + (tx & 3)*4;
    #pragma unroll
    for (int i = 0; i < 4; i++) {
        int n = ty*4 + i;
        float4 v = make_float4(acc[i][0], acc[i][1], acc[i][2], acc[i][3]);
        *(float4*)&part[((size_t)(slot*NBATCH + n))*G4 + col0] = v;
    }
}

// ---------------- encoder pointwise (4 K-partials per dir) ----------------
__global__ __launch_bounds__(512)
void enc_pointwise_kernel(const float* __restrict__ part,
                          const float* __restrict__ xp0, const float* __restrict__ xp1,
                          const float* __restrict__ cin,
                          float* __restrict__ hout, float* __restrict__ cout,
                          float* __restrict__ es0, float* __restrict__ es1)
{
    const int n = blockIdx.x, dir = blockIdx.y, j = threadIdx.x;
    const float* xp = dir ? xp1 : xp0;
    float g4[4];
    #pragma unroll
    for (int g = 0; g < 4; g++) {
        size_t o = (size_t)n*G4 + g*HDIM + j;
        g4[g] = part[(size_t)(0*2+dir)*NG4 + o] + part[(size_t)(1*2+dir)*NG4 + o]
              + part[(size_t)(2*2+dir)*NG4 + o] + part[(size_t)(3*2+dir)*NG4 + o] + xp[o];
    }
    float ig = 1.f/(1.f+expf(-g4[0]));
    float fg = 1.f/(1.f+expf(-g4[1]));
    float gg = tanhf(g4[2]);
    float og = 1.f/(1.f+expf(-g4[3]));
    float cn = fg * cin[(dir*NBATCH+n)*HDIM + j] + ig*gg;
    float hn = og * tanhf(cn);
    cout[(dir*NBATCH+n)*HDIM + j] = cn;
    hout[(dir*NBATCH+n)*HDIM + j] = hn;
    float* es = dir ? es1 : es0;
    es[(size_t)n*ESDIM + j] = hn;
}

// ---------------- decoder fused: blocks 0-127 gate GEMM (split-K4), 128-191 attention+ctx ----------------
__global__ __launch_bounds__(512)
void dec_gemm_ctx_kernel(const float* __restrict__ hin,
                         const float* __restrict__ W,       // dWhh [2048][512]
                         const float* __restrict__ eW,
                         const float* __restrict__ ebias,
                         float* __restrict__ part)
{
    const int bx = blockIdx.x;
    const int tid = threadIdx.x;

    if (bx < 128) {
        // ---- gate GEMM slice (256 active threads) ----
        __shared__ float hs[16][68];
        __shared__ float ws[16][68];
        const int jt = bx & 31;
        const int kc = bx >> 5;          // 0..3
        const int kbeg = kc * 128;
        const int j0 = jt * 16;

        const int r  = tid >> 2;         // valid for tid<256
        const int kq = tid & 3;
        const int wrow = (r >> 4) * HDIM + j0 + (r & 15);
        const int tx = tid & 15, ty = tid >> 4;

        const float* Aptr = hin + (size_t)r * HDIM + kbeg + kq*4;
        const float* Wptr = W + (size_t)wrow * HDIM + kbeg + kq*4;

        float4 fa = make_float4(0.f,0.f,0.f,0.f);
        float4 fw = make_float4(0.f,0.f,0.f,0.f);
        if (tid < 256) { fa = *(const float4*)Aptr; fw = *(const float4*)Wptr; }

        float acc[4][4] = {};
        const int ktiles = 8;            // 128/16

        for (int t = 0; t < ktiles; t++) {
            if (tid < 256) {
                hs[kq*4+0][r] = fa.x; hs[kq*4+1][r] = fa.y; hs[kq*4+2][r] = fa.z; hs[kq*4+3][r] = fa.w;
                ws[kq*4+0][r] = fw.x; ws[kq*4+1][r] = fw.y; ws[kq*4+2][r] = fw.z; ws[kq*4+3][r] = fw.w;
            }
            __syncthreads();
            if (tid < 256) {
                if (t + 1 < ktiles) {
                    fa = *(const float4*)(Aptr + (t+1)*16);
                    fw = *(const float4*)(Wptr + (t+1)*16);
                }
                #pragma unroll
                for (int kk = 0; kk < 16; kk++) {
                    float4 av = *(const float4*)&hs[kk][ty*4];
                    float4 bv = *(const float4*)&ws[kk][tx*4];
                    acc[0][0] += av.x*bv.x; acc[0][1] += av.x*bv.y; acc[0][2] += av.x*bv.z; acc[0][3] += av.x*bv.w;
                    acc[1][0] += av.y*bv.x; acc[1][1] += av.y*bv.y; acc[1][2] += av.y*bv.z; acc[1][3] += av.y*bv.w;
                    acc[2][0] += av.z*bv.x; acc[2][1] += av.z*bv.y; acc[2][2] += av.z*bv.z; acc[2][3] += av.z*bv.w;
                    acc[3][0] += av.w*bv.x; acc[3][1] += av.w*bv.y; acc[3][2] += av.w*bv.z; acc[3][3] += av.w*bv.w;
                }
            }
            __syncthreads();
        }

        if (tid < 256) {
            const int gate = tx >> 2;
            const int col0 = gate*HDIM + j0 + (tx & 3)*4;
            #pragma unroll
            for (int i = 0; i < 4; i++) {
                int n = ty*4 + i;
                float4 v = make_float4(acc[i][0], acc[i][1], acc[i][2], acc[i][3]);
                *(float4*)&part[((size_t)(kc*NBATCH + n))*G4 + col0] = v;
            }
        }
    } else {
        // ---- attention + ctx for one batch element ----
        __shared__ float red[16];
        __shared__ float earr[SS];
        __shared__ float sc[1];
        const int n = bx - 128;
        const int j = tid;

        float p = hin[n*HDIM + j] * eW[j];
        #pragma unroll
        for (int o = 16; o; o >>= 1) p += __shfl_xor_sync(0xffffffffu, p, o);
        if ((j & 31) == 0) red[j >> 5] = p;
        __syncthreads();
        if (j == 0) { float s = 0.f; for (int i = 0; i < 16; i++) s += red[i]; sc[0] = s; }
        __syncthreads();
        float hdot = sc[0];
        if (j < SS) {
            float e = hdot + g_esproj[j*NBATCH + n] + ebias[0];
            earr[j] = e > 0.f ? e : 0.f;
        }
        __syncthreads();
        if (j == 0) {
            float m = earr[0];
            for (int s = 1; s < SS; s++) m = fmaxf(m, earr[s]);
            float sum = 0.f;
            for (int s = 0; s < SS; s++) { float v = expf(earr[s]-m); earr[s] = v; sum += v; }
            sc[0] = 1.f / sum;
        }
        __syncthreads();
        float inv = sc[0];

        // ctx contribution into partial slot 4: thread covers cols [4j,4j+4)
        float4 a = make_float4(0.f, 0.f, 0.f, 0.f);
        for (int s = 0; s < SS; s++) {
            float w = earr[s];
            float4 v = *(const float4*)(g_esw + ((size_t)(s*NBATCH + n))*G4 + j*4);
            a.x += w*v.x; a.y += w*v.y; a.z += w*v.z; a.w += w*v.w;
        }
        float4 o4 = make_float4(a.x*inv, a.y*inv, a.z*inv, a.w*inv);
        *(float4*)&part[(size_t)(4*NBATCH + n)*G4 + j*4] = o4;
    }
}

// ---------------- decoder pointwise: gates = 4 K-partials + ctx + dxp ----------------
__global__ __launch_bounds__(512)
void dec_pw_kernel(const float* __restrict__ part,
                   const float* __restrict__ dxp,
                   const float* __restrict__ cin,
                   float* __restrict__ hout,
                   float* __restrict__ cout,
                   float* __restrict__ hist)
{
    const int n = blockIdx.x, j = threadIdx.x;
    float g4[4];
    #pragma unroll
    for (int g = 0; g < 4; g++) {
        size_t o = (size_t)n*G4 + g*HDIM + j;
        g4[g] = part[o] + part[(size_t)NG4 + o] + part[(size_t)2*NG4 + o]
              + part[(size_t)3*NG4 + o] + part[(size_t)4*NG4 + o] + dxp[o];
    }
    float ig = 1.f/(1.f+expf(-g4[0]));
    float fg = 1.f/(1.f+expf(-g4[1]));
    float gg = tanhf(g4[2]);
    float og = 1.f/(1.f+expf(-g4[3]));
    float cn = fg * cin[n*HDIM + j] + ig*gg;
    float hn = og * tanhf(cn);
    cout[n*HDIM + j] = cn;
    hout[n*HDIM + j] = hn;
    hist[n*HDIM + j] = hn;
}

// ---------------- attention pre-projection ----------------
__global__ void esproj_kernel(const float* __restrict__ eW){
    int gw = (blockIdx.x*blockDim.x + threadIdx.x) >> 5;
    int lane = threadIdx.x & 31;
    if (gw >= SS*NBATCH) return;
    const float* row = g_es + (size_t)gw*ESDIM;
    const float* We  = eW + HDIM;
    float p = 0.f;
    for (int k = lane; k < ESDIM; k += 32) p += row[k] * We[k];
    #pragma unroll
    for (int o = 16; o; o >>= 1) p += __shfl_xor_sync(0xffffffffu, p, o);
    if (lane == 0) g_esproj[gw] = p;
}

// ---------------- host orchestration ----------------
extern "C" void kernel_launch(void* const* d_in, const int* in_sizes, int n_in,
                              void* d_out, int out_size)
{
    (void)in_sizes; (void)n_in; (void)out_size;
    const int*   src     = (const int*)  d_in[0];
    const int*   tgt     = (const int*)  d_in[1];
    const float* enc_emb = (const float*)d_in[2];
    const float* Wih_f   = (const float*)d_in[3];
    const float* Whh_f   = (const float*)d_in[4];
    const float* b_f     = (const float*)d_in[5];
    const float* Wih_b   = (const float*)d_in[6];
    const float* Whh_b   = (const float*)d_in[7];
    const float* b_b     = (const float*)d_in[8];
    const float* fcW_h   = (const float*)d_in[9];
    const float* fcb_h   = (const float*)d_in[10];
    const float* fcW_c   = (const float*)d_in[11];
    const float* fcb_c   = (const float*)d_in[12];
    const float* dec_emb = (const float*)d_in[13];
    const float* dWih    = (const float*)d_in[14];
    const float* dWhh    = (const float*)d_in[15];
    const float* db      = (const float*)d_in[16];
    const float* eW      = (const float*)d_in[17];
    const float* ebias   = (const float*)d_in[18];
    const float* fcW     = (const float*)d_in[19];
    const float* fcb     = (const float*)d_in[20];
    float* out = (float*)d_out;

    float *p_emb, *p_demb, *p_xpf, *p_xpb, *p_dxp, *p_es, *p_h, *p_c,
          *p_hcat, *p_ccat, *p_dh, *p_dc, *p_esw, *p_hhist, *p_part, *p_zb;
    unsigned short *p_abig, *p_bbig, *p_ea2, *p_da2, *p_wf2, *p_wb2, *p_wd2, *p_es3, *p_wc3;
    cudaGetSymbolAddress((void**)&p_emb,   g_emb_src);
    cudaGetSymbolAddress((void**)&p_demb,  g_demb);
    cudaGetSymbolAddress((void**)&p_xpf,   g_xpf);
    cudaGetSymbolAddress((void**)&p_xpb,   g_xpb);
    cudaGetSymbolAddress((void**)&p_dxp,   g_dxp);
    cudaGetSymbolAddress((void**)&p_es,    g_es);
    cudaGetSymbolAddress((void**)&p_h,     g_h_enc);
    cudaGetSymbolAddress((void**)&p_c,     g_c_enc);
    cudaGetSymbolAddress((void**)&p_hcat,  g_hcat);
    cudaGetSymbolAddress((void**)&p_ccat,  g_ccat);
    cudaGetSymbolAddress((void**)&p_dh,    g_dec_h);
    cudaGetSymbolAddress((void**)&p_dc,    g_dec_c);
    cudaGetSymbolAddress((void**)&p_esw,   g_esw);
    cudaGetSymbolAddress((void**)&p_hhist, g_hhist);
    cudaGetSymbolAddress((void**)&p_part,  g_part);
    cudaGetSymbolAddress((void**)&p_zb,    g_zb);
    cudaGetSymbolAddress((void**)&p_abig,  g_abig);
    cudaGetSymbolAddress((void**)&p_bbig,  g_bbig);
    cudaGetSymbolAddress((void**)&p_ea2,   g_ea2);
    cudaGetSymbolAddress((void**)&p_da2,   g_da2);
    cudaGetSymbolAddress((void**)&p_wf2,   g_wf2);
    cudaGetSymbolAddress((void**)&p_wb2,   g_wb2);
    cudaGetSymbolAddress((void**)&p_wd2,   g_wd2);
    cudaGetSymbolAddress((void**)&p_es3,   g_es3);
    cudaGetSymbolAddress((void**)&p_wc3,   g_wc3);

    // ---- Phase A (launch #4 = gemm_tc for ncu capture) ----
    embed_kernel<<<(SS*NBATCH*EDIM + 255)/256, 256>>>(src, enc_emb, p_emb, SS*NBATCH);   // 1
    convA2_kernel<<<(SS*NBATCH*KP + 255)/256, 256>>>(p_emb, p_ea2, SS*NBATCH);           // 2
    convW2_kernel<<<(G4*KP + 255)/256, 256>>>(Wih_f, p_wf2, EDIM, 0);                    // 3
    gemm_tc_kernel<<<dim3(16, 25), 256>>>(p_ea2, p_wf2, b_f, p_xpf, SS*NBATCH, G4, KBIG2); // 4 (profiled)
    convB_kernel<<<(VTGT*HDIM + 255)/256, 256>>>(fcW);
    embed_kernel<<<(TDEC*NBATCH*EDIM + 255)/256, 256>>>(tgt, dec_emb, p_demb, TDEC*NBATCH);
    convA2_kernel<<<(TDEC*NBATCH*KP + 255)/256, 256>>>(p_demb, p_da2, TDEC*NBATCH);
    convW2_kernel<<<(G4*KP + 255)/256, 256>>>(Wih_b, p_wb2, EDIM, 0);
    convW2_kernel<<<(G4*KP + 255)/256, 256>>>(dWih, p_wd2, 2*HDIM + EDIM, ESDIM);
    gemm_tc_kernel<<<dim3(16, 25), 256>>>(p_ea2, p_wb2, b_b, p_xpb, SS*NBATCH, G4, KBIG2);
    gemm_tc_kernel<<<dim3(16, 25), 256>>>(p_da2, p_wd2, db, p_dxp, TDEC*NBATCH, G4, KBIG2);
    convW3_kernel<<<(G4*ESDIM + 255)/256, 256>>>(dWih, 2*HDIM + EDIM);  // Wih_ctx (K=1024)
    zero_kernel<<<(G4 + 255)/256, 256>>>(p_zb, G4);
    zero_kernel<<<(2*NH + 255)/256, 256>>>(p_h, 2*NH);
    zero_kernel<<<(2*NH + 255)/256, 256>>>(p_c, 2*NH);

    // ---- Phase B: encoder recurrence (launch-based, fused fwd+bwd, split-K4) ----
    for (int s = 0; s < SS; s++) {
        int pin = s & 1, pout = pin ^ 1;
        lstm_gemm_kernel<<<dim3(32, 4, 2), 256>>>(
            p_h + (pin*2+0)*NH, p_h + (pin*2+1)*NH, HDIM,
            Whh_f, Whh_b, HDIM, 128, p_part);
        enc_pointwise_kernel<<<dim3(NBATCH, 2), 512>>>(
            p_part,
            p_xpf + (size_t)s*NG4, p_xpb + (size_t)(SS-1-s)*NG4,
            p_c + pin*2*NH, p_h + pout*2*NH, p_c + pout*2*NH,
            p_es + (size_t)s*NBATCH*ESDIM,
            p_es + (size_t)(SS-1-s)*NBATCH*ESDIM + HDIM);
    }

    // ---- Bridge + attention precomputation ----
    hccat_kernel<<<(NBATCH*ESDIM + 255)/256, 256>>>();
    gemm_kernel<<<dim3(8, 1), 256>>>(p_hcat, ESDIM, fcW_h, ESDIM, fcb_h,
                                     p_dh, HDIM, NBATCH, HDIM, ESDIM);
    gemm_kernel<<<dim3(8, 1), 256>>>(p_ccat, ESDIM, fcW_c, ESDIM, fcb_c,
                                     p_dc, HDIM, NBATCH, HDIM, ESDIM);
    esproj_kernel<<<(SS*NBATCH*32 + 255)/256, 256>>>(eW);
    convES_kernel<<<(SS*NBATCH*ESDIM + 255)/256, 256>>>();
    gemm_tc_kernel<<<dim3(16, 25), 256>>>(p_es3, p_wc3, p_zb, p_esw,
                                          SS*NBATCH, G4, KBIG3);

    // ---- Phase C: decoder recurrence (fused GEMM∥attention+ctx, then pointwise) ----
    for (int t = 0; t < TDEC; t++) {
        int pin = t & 1, pout = pin ^ 1;
        dec_gemm_ctx_kernel<<<192, 512>>>(
            p_dh + pin*NH, dWhh, eW, ebias, p_part);
        dec_pw_kernel<<<NBATCH, 512>>>(
            p_part, p_dxp + (size_t)t*NG4,
            p_dc + pin*NH,
            p_dh + pout*NH, p_dc + pout*NH,
            p_hhist + (size_t)t*NH);
    }

    // ---- Phase D: output — bf16-split tensor-core GEMM ----
    zero_kernel<<<(NBATCH*VTGT + 255)/256, 256>>>(out, NBATCH*VTGT);
    convA_kernel<<<(MOUT*HDIM + 255)/256, 256>>>(p_hhist);
    gemm_tc_kernel<<<dim3((VTGT + 127)/128, (MOUT + 127)/128), 256>>>(
        p_abig, p_bbig, fcb, out + (size_t)NBATCH*VTGT, MOUT, VTGT, KBIG);
}

// round 15
// speedup vs baseline: 1.4630x; 1.4630x over previous
#include <cuda_runtime.h>
#include <math.h>

#define SS      50
#define NBATCH  64
#define EDIM    300
#define HDIM    512
#define G4      2048
#define ESDIM   1024
#define VTGT    10000
#define TDEC    49
#define NH      (NBATCH*HDIM)
#define NG4     (NBATCH*G4)
#define MOUT    (TDEC*NBATCH)
#define KBIG    1536
#define KP      320
#define KBIG2   960
#define KBIG3   3072
#define BST2    40

// ---------------- scratch (device globals; no runtime allocation) ----------------
__device__ float g_emb_src[SS*NBATCH*EDIM];
__device__ float g_demb  [TDEC*NBATCH*EDIM];
__device__ float g_xpf   [SS*NBATCH*G4];
__device__ float g_xpb   [SS*NBATCH*G4];
__device__ float g_dxp   [TDEC*NBATCH*G4];
__device__ float g_es    [SS*NBATCH*ESDIM];
__device__ float g_h_enc [2*2*NBATCH*HDIM];   // [parity][dir][n][h]
__device__ float g_c_enc [2*2*NBATCH*HDIM];
__device__ float g_hcat  [NBATCH*ESDIM];
__device__ float g_ccat  [NBATCH*ESDIM];
__device__ float g_dec_h [2*NBATCH*HDIM];
__device__ float g_dec_c [2*NBATCH*HDIM];
__device__ float g_esproj[SS*NBATCH];
__device__ float g_esw   [SS*NBATCH*G4];      // es[s,n,:]·Wih_ctx^T
__device__ float g_hhist [TDEC*NBATCH*HDIM];
__device__ float g_part  [8*NBATCH*G4];       // slots 0-3: K-partials, slot 4: ctx
__device__ float g_zb    [G4];
__device__ unsigned short g_abig[MOUT*KBIG];      // bf16 bits: [Ah|Ah|Al]
__device__ unsigned short g_bbig[VTGT*KBIG];      // bf16 bits: [Bh|Bl|Bh]
__device__ unsigned short g_ea2 [SS*NBATCH*KBIG2];
__device__ unsigned short g_da2 [TDEC*NBATCH*KBIG2];
__device__ unsigned short g_wf2 [G4*KBIG2];
__device__ unsigned short g_wb2 [G4*KBIG2];
__device__ unsigned short g_wd2 [G4*KBIG2];
__device__ unsigned short g_es3 [SS*NBATCH*KBIG3];
__device__ unsigned short g_wc3 [G4*KBIG3];

// ---------------- bf16 bit helpers (round-to-nearest-even) ----------------
__device__ __forceinline__ unsigned short f2bf(float x){
    unsigned int u = __float_as_uint(x);
    unsigned int r = (u + 0x7fffu + ((u >> 16) & 1u)) >> 16;
    return (unsigned short)r;
}
__device__ __forceinline__ float bf2f(unsigned short b){
    return __uint_as_float(((unsigned int)b) << 16);
}

// ---------------- small utility kernels ----------------
__global__ void zero_kernel(float* __restrict__ p, int n){
    int i = blockIdx.x*blockDim.x + threadIdx.x;
    if (i < n) p[i] = 0.f;
}

__global__ void embed_kernel(const int* __restrict__ tok,
                             const float* __restrict__ table,
                             float* __restrict__ out, int rows){
    int i = blockIdx.x*blockDim.x + threadIdx.x;
    int total = rows * EDIM;
    if (i >= total) return;
    int r = i / EDIM, e = i - r*EDIM;
    out[i] = table[(size_t)tok[r]*EDIM + e];
}

__global__ void hccat_kernel(){
    int i = blockIdx.x*blockDim.x + threadIdx.x;
    if (i >= NBATCH*ESDIM) return;
    int n = i >> 10, k = i & 1023;
    int src = (k < HDIM) ? (0*NH + n*HDIM + k)
                         : (1*NH + n*HDIM + (k - HDIM));
    g_hcat[i] = g_h_enc[src];
    g_ccat[i] = g_c_enc[src];
}

// Phase-D conversions (K=512 splits, KBIG=1536)
__global__ void convA_kernel(const float* __restrict__ X){
    int i = blockIdx.x*blockDim.x + threadIdx.x;
    if (i >= MOUT*HDIM) return;
    int m = i >> 9, k = i & 511;
    float x = X[i];
    unsigned short hi = f2bf(x);
    unsigned short lo = f2bf(x - bf2f(hi));
    g_abig[(size_t)m*KBIG + k]        = hi;
    g_abig[(size_t)m*KBIG + 512 + k]  = hi;
    g_abig[(size_t)m*KBIG + 1024 + k] = lo;
}

__global__ void convB_kernel(const float* __restrict__ W){
    int i = blockIdx.x*blockDim.x + threadIdx.x;
    if (i >= VTGT*HDIM) return;
    int n = i >> 9, k = i & 511;
    float x = W[i];
    unsigned short hi = f2bf(x);
    unsigned short lo = f2bf(x - bf2f(hi));
    g_bbig[(size_t)n*KBIG + k]        = hi;
    g_bbig[(size_t)n*KBIG + 512 + k]  = lo;
    g_bbig[(size_t)n*KBIG + 1024 + k] = hi;
}

// Phase-A conversions (K=300 padded to 320, KBIG2=960)
__global__ void convA2_kernel(const float* __restrict__ X,
                              unsigned short* __restrict__ dst, int rows){
    int i = blockIdx.x*blockDim.x + threadIdx.x;
    if (i >= rows*KP) return;
    int m = i / KP, k = i - m*KP;
    unsigned short hi = 0, lo = 0;
    if (k < EDIM){
        float x = X[(size_t)m*EDIM + k];
        hi = f2bf(x);
        lo = f2bf(x - bf2f(hi));
    }
    dst[(size_t)m*KBIG2 + k]        = hi;
    dst[(size_t)m*KBIG2 + KP + k]   = hi;
    dst[(size_t)m*KBIG2 + 2*KP + k] = lo;
}

__global__ void convW2_kernel(const float* __restrict__ W,
                              unsigned short* __restrict__ dst, int ldw, int koff){
    int i = blockIdx.x*blockDim.x + threadIdx.x;
    if (i >= G4*KP) return;
    int n = i / KP, k = i - n*KP;
    unsigned short hi = 0, lo = 0;
    if (k < EDIM){
        float x = W[(size_t)n*ldw + koff + k];
        hi = f2bf(x);
        lo = f2bf(x - bf2f(hi));
    }
    dst[(size_t)n*KBIG2 + k]        = hi;
    dst[(size_t)n*KBIG2 + KP + k]   = lo;
    dst[(size_t)n*KBIG2 + 2*KP + k] = hi;
}

// esW conversions (K=1024, KBIG3=3072)
__global__ void convES_kernel(){
    int i = blockIdx.x*blockDim.x + threadIdx.x;
    if (i >= SS*NBATCH*ESDIM) return;
    int m = i >> 10, k = i & 1023;
    float x = g_es[i];
    unsigned short hi = f2bf(x);
    unsigned short lo = f2bf(x - bf2f(hi));
    g_es3[(size_t)m*KBIG3 + k]        = hi;
    g_es3[(size_t)m*KBIG3 + 1024 + k] = hi;
    g_es3[(size_t)m*KBIG3 + 2048 + k] = lo;
}

__global__ void convW3_kernel(const float* __restrict__ W, int ldw){
    int i = blockIdx.x*blockDim.x + threadIdx.x;
    if (i >= G4*ESDIM) return;
    int n = i >> 10, k = i & 1023;
    float x = W[(size_t)n*ldw + k];
    unsigned short hi = f2bf(x);
    unsigned short lo = f2bf(x - bf2f(hi));
    g_wc3[(size_t)n*KBIG3 + k]        = hi;
    g_wc3[(size_t)n*KBIG3 + 1024 + k] = lo;
    g_wc3[(size_t)n*KBIG3 + 2048 + k] = hi;
}

// ---------------- small fp32 GEMM (bridge only): C[M,N] = A*B^T + bias ----------------
__global__ __launch_bounds__(256)
void gemm_kernel(const float* __restrict__ A, int lda,
                 const float* __restrict__ B, int ldb,
                 const float* __restrict__ bias,
                 float* __restrict__ C, int ldc,
                 int M, int N, int K)
{
    __shared__ float As[8][68];
    __shared__ float Bs[8][68];
    const int tid = threadIdx.x;
    const int tx = tid & 15, ty = tid >> 4;
    const int mb = blockIdx.y * 64, nb = blockIdx.x * 64;
    float acc[4][4] = {};

    for (int k0 = 0; k0 < K; k0 += 8) {
        #pragma unroll
        for (int i = 0; i < 2; i++) {
            int idx = tid + i*256;
            int kk = idx & 7, rr = idx >> 3;
            int m = mb + rr, k = k0 + kk;
            As[kk][rr] = (m < M && k < K) ? A[(size_t)m*lda + k] : 0.f;
            int nn = nb + rr;
            Bs[kk][rr] = (nn < N && k < K) ? B[(size_t)nn*ldb + k] : 0.f;
        }
        __syncthreads();
        #pragma unroll
        for (int kk = 0; kk < 8; kk++) {
            float a0 = As[kk][ty*4+0], a1 = As[kk][ty*4+1];
            float a2 = As[kk][ty*4+2], a3 = As[kk][ty*4+3];
            float b0 = Bs[kk][tx*4+0], b1 = Bs[kk][tx*4+1];
            float b2 = Bs[kk][tx*4+2], b3 = Bs[kk][tx*4+3];
            acc[0][0] += a0*b0; acc[0][1] += a0*b1; acc[0][2] += a0*b2; acc[0][3] += a0*b3;
            acc[1][0] += a1*b0; acc[1][1] += a1*b1; acc[1][2] += a1*b2; acc[1][3] += a1*b3;
            acc[2][0] += a2*b0; acc[2][1] += a2*b1; acc[2][2] += a2*b2; acc[2][3] += a2*b3;
            acc[3][0] += a3*b0; acc[3][1] += a3*b1; acc[3][2] += a3*b2; acc[3][3] += a3*b3;
        }
        __syncthreads();
    }
    #pragma unroll
    for (int i = 0; i < 4; i++) {
        int m = mb + ty*4 + i;
        if (m >= M) continue;
        #pragma unroll
        for (int j = 0; j < 4; j++) {
            int nn = nb + tx*4 + j;
            if (nn >= N) continue;
            C[(size_t)m*ldc + nn] = acc[i][j] + (bias ? bias[nn] : 0.f);
        }
    }
}

// ---------------- tensor-core bf16-split GEMM: 32-wide K stages ----------------
__device__ __forceinline__ void ldsm_x4(unsigned int* r, unsigned int addr){
    asm volatile("ldmatrix.sync.aligned.m8n8.x4.shared.b16 {%0,%1,%2,%3}, [%4];"
        : "=r"(r[0]), "=r"(r[1]), "=r"(r[2]), "=r"(r[3]) : "r"(addr));
}
__device__ __forceinline__ void mma16816(float* c, const unsigned int* a, const unsigned int* b){
    asm volatile("mma.sync.aligned.m16n8k16.row.col.f32.bf16.bf16.f32 "
        "{%0,%1,%2,%3}, {%4,%5,%6,%7}, {%8,%9}, {%0,%1,%2,%3};"
        : "+f"(c[0]), "+f"(c[1]), "+f"(c[2]), "+f"(c[3])
        : "r"(a[0]), "r"(a[1]), "r"(a[2]), "r"(a[3]), "r"(b[0]), "r"(b[1]));
}

__global__ __launch_bounds__(256)
void gemm_tc_kernel(const unsigned short* __restrict__ A,
                    const unsigned short* __restrict__ B,
                    const float* __restrict__ bias,
                    float* __restrict__ C, int M, int N, int K)
{
    __shared__ __align__(16) unsigned short As[2*128*BST2];
    __shared__ __align__(16) unsigned short Bs[2*128*BST2];
    const int tid  = threadIdx.x;
    const int mb   = blockIdx.y * 128;
    const int nb   = blockIdx.x * 128;
    const int warp = tid >> 5;
    const int lane = tid & 31;
    const int wm   = warp & 1;        // 2x4 warp grid; warp tile 64x32
    const int wn   = warp >> 1;

    const int lrow = tid >> 1;        // 0..127
    const int lks  = (tid & 1) * 16;  // shorts offset within 32-wide K stage

    const int arow = (mb + lrow < M);
    const int brow = (nb + lrow < N);
    const unsigned short* aptr = A + (size_t)(arow ? (mb + lrow) : 0)*K + lks;
    const unsigned short* bptr = B + (size_t)(brow ? (nb + lrow) : 0)*K + lks;

    // stage 0
    {
        float4 a0 = make_float4(0.f,0.f,0.f,0.f), a1 = a0, b0 = a0, b1 = a0;
        if (arow) { a0 = *(const float4*)(aptr); a1 = *(const float4*)(aptr + 8); }
        if (brow) { b0 = *(const float4*)(bptr); b1 = *(const float4*)(bptr + 8); }
        *(float4*)&As[lrow*BST2 + lks]     = a0;
        *(float4*)&As[lrow*BST2 + lks + 8] = a1;
        *(float4*)&Bs[lrow*BST2 + lks]     = b0;
        *(float4*)&Bs[lrow*BST2 + lks + 8] = b1;
    }
    __syncthreads();

    float acc[4][4][4];
    #pragma unroll
    for (int i = 0; i < 4; i++)
        #pragma unroll
        for (int j = 0; j < 4; j++) {
            acc[i][j][0] = 0.f; acc[i][j][1] = 0.f;
            acc[i][j][2] = 0.f; acc[i][j][3] = 0.f;
        }

    const int fr  = (lane & 7) + ((lane >> 3) & 1) * 8;   // A: row within 16
    const int fcA = ((lane >> 4) & 1) * 8;                // A: k-half
    const int frB = (lane & 7) + ((lane >> 4) & 1) * 8;   // B: n row within 16
    const int fcB = ((lane >> 3) & 1) * 8;                // B: k-half

    const unsigned int a_base = (unsigned int)__cvta_generic_to_shared(&As[0]);
    const unsigned int b_base = (unsigned int)__cvta_generic_to_shared(&Bs[0]);
    const unsigned int stage_bytes = 128u * BST2 * 2u;

    const int NT = K / 32;
    for (int t = 0; t < NT; t++) {
        const int buf = t & 1;
        const unsigned int ab = a_base + (unsigned int)buf * stage_bytes;
        const unsigned int bb = b_base + (unsigned int)buf * stage_bytes;
        const unsigned int nab = a_base + (unsigned int)(buf ^ 1) * stage_bytes;
        const unsigned int nbb = b_base + (unsigned int)(buf ^ 1) * stage_bytes;

        // ---- k-half 0 ----
        {
            unsigned int areg[4][4];
            unsigned int breg[4][2];
            #pragma unroll
            for (int i = 0; i < 4; i++) {
                int row = wm*64 + i*16 + fr;
                ldsm_x4(areg[i], ab + (unsigned int)(row*BST2 + fcA) * 2u);
            }
            #pragma unroll
            for (int p = 0; p < 2; p++) {
                int row = wn*32 + p*16 + frB;
                unsigned int r4[4];
                ldsm_x4(r4, bb + (unsigned int)(row*BST2 + fcB) * 2u);
                breg[p*2][0]   = r4[0];
                breg[p*2][1]   = r4[1];
                breg[p*2+1][0] = r4[2];
                breg[p*2+1][1] = r4[3];
            }
            #pragma unroll
            for (int i = 0; i < 4; i++)
                #pragma unroll
                for (int j = 0; j < 4; j++)
                    mma16816(acc[i][j], areg[i], breg[j]);
        }

        // prefetch A for next stage (overlaps with MMA above/below)
        if (t + 1 < NT) {
            const int k0 = (t + 1) * 32;
            float4 a0 = make_float4(0.f,0.f,0.f,0.f), a1 = a0;
            if (arow) { a0 = *(const float4*)(aptr + k0); a1 = *(const float4*)(aptr + k0 + 8); }
            *(float4*)&As[(buf^1)*128*BST2 + lrow*BST2 + lks]     = a0;
            *(float4*)&As[(buf^1)*128*BST2 + lrow*BST2 + lks + 8] = a1;
        }

        // ---- k-half 1 ----
        {
            unsigned int areg[4][4];
            unsigned int breg[4][2];
            #pragma unroll
            for (int i = 0; i < 4; i++) {
                int row = wm*64 + i*16 + fr;
                ldsm_x4(areg[i], ab + (unsigned int)(row*BST2 + 16 + fcA) * 2u);
            }
            #pragma unroll
            for (int p = 0; p < 2; p++) {
                int row = wn*32 + p*16 + frB;
                unsigned int r4[4];
                ldsm_x4(r4, bb + (unsigned int)(row*BST2 + 16 + fcB) * 2u);
                breg[p*2][0]   = r4[0];
                breg[p*2][1]   = r4[1];
                breg[p*2+1][0] = r4[2];
                breg[p*2+1][1] = r4[3];
            }
            #pragma unroll
            for (int i = 0; i < 4; i++)
                #pragma unroll
                for (int j = 0; j < 4; j++)
                    mma16816(acc[i][j], areg[i], breg[j]);
        }

        // prefetch B for next stage
        if (t + 1 < NT) {
            const int k0 = (t + 1) * 32;
            float4 b0 = make_float4(0.f,0.f,0.f,0.f), b1 = b0;
            if (brow) { b0 = *(const float4*)(bptr + k0); b1 = *(const float4*)(bptr + k0 + 8); }
            *(float4*)&Bs[(buf^1)*128*BST2 + lrow*BST2 + lks]     = b0;
            *(float4*)&Bs[(buf^1)*128*BST2 + lrow*BST2 + lks + 8] = b1;
        }
        __syncthreads();
        (void)nab; (void)nbb;
    }

    const int er = lane >> 2;
    const int ec = (lane & 3) * 2;
    #pragma unroll
    for (int i = 0; i < 4; i++) {
        #pragma unroll
        for (int j = 0; j < 4; j++) {
            int m0 = mb + wm*64 + i*16 + er;
            int n0 = nb + wn*32 + j*8 + ec;
            if (n0 < N) {
                if (m0 < M) {
                    C[(size_t)m0*N + n0] = acc[i][j][0] + bias[n0];
                    if (n0+1 < N) C[(size_t)m0*N + n0+1] = acc[i][j][1] + bias[n0+1];
                }
                if (m0+8 < M) {
                    C[(size_t)(m0+8)*N + n0] = acc[i][j][2] + bias[n0];
                    if (n0+1 < N) C[(size_t)(m0+8)*N + n0+1] = acc[i][j][3] + bias[n0+1];
                }
            }
        }
    }
}

// ---------------- LSTM gate GEMM (split-K, dual input): partial[slot][n][2048] ----------------
__global__ __launch_bounds__(256)
void lstm_gemm_kernel(const float* __restrict__ A0, const float* __restrict__ A1, int lda,
                      const float* __restrict__ W0, const float* __restrict__ W1, int ldw,
                      int kchunk, float* __restrict__ part)
{
    __shared__ float hs[16][68];
    __shared__ float ws[16][68];
    const int tid = threadIdx.x;
    const int dir = blockIdx.z;
    const int slot = blockIdx.y * gridDim.z + blockIdx.z;
    const float* __restrict__ A = dir ? A1 : A0;
    const float* __restrict__ W = dir ? W1 : W0;
    const int kbeg = blockIdx.y * kchunk;
    const int j0 = blockIdx.x * 16;

    const int r  = tid >> 2;
    const int kq = tid & 3;
    const int wrow = (r >> 4) * HDIM + j0 + (r & 15);
    const int tx = tid & 15, ty = tid >> 4;

    const float* Aptr = A + (size_t)r * lda + kbeg + kq*4;
    const float* Wptr = W + (size_t)wrow * ldw + kbeg + kq*4;

    float4 fa = *(const float4*)Aptr;
    float4 fw = *(const float4*)Wptr;

    float acc[4][4] = {};
    const int ktiles = kchunk / 16;

    for (int t = 0; t < ktiles; t++) {
        hs[kq*4+0][r] = fa.x; hs[kq*4+1][r] = fa.y; hs[kq*4+2][r] = fa.z; hs[kq*4+3][r] = fa.w;
        ws[kq*4+0][r] = fw.x; ws[kq*4+1][r] = fw.y; ws[kq*4+2][r] = fw.z; ws[kq*4+3][r] = fw.w;
        __syncthreads();
        if (t + 1 < ktiles) {
            fa = *(const float4*)(Aptr + (t+1)*16);
            fw = *(const float4*)(Wptr + (t+1)*16);
        }
        #pragma unroll
        for (int kk = 0; kk < 16; kk++) {
            float4 av = *(const float4*)&hs[kk][ty*4];
            float4 bv = *(const float4*)&ws[kk][tx*4];
            acc[0][0] += av.x*bv.x; acc[0][1] += av.x*bv.y; acc[0][2] += av.x*bv.z; acc[0][3] += av.x*bv.w;
            acc[1][0] += av.y*bv.x; acc[1][1] += av.y*bv.y; acc[1][2] += av.y*bv.z; acc[1][3] += av.y*bv.w;
            acc[2][0] += av.z*bv.x; acc[2][1] += av.z*bv.y; acc[2][2] += av.z*bv.z; acc[2][3] += av.z*bv.w;
            acc[3][0] += av.w*bv.x; acc[3][1] += av.w*bv.y; acc[3][2] += av.w*bv.z; acc[3][3] += av.w*bv.w;
        }
        __syncthreads();
    }

    const int gate = tx >> 2;
    const int col0 = gate*HDIM + j0 + (tx & 3)*4;
    #pragma unroll
    for (int i = 0; i < 4; i++) {
        int n = ty*4 + i;
        float4 v = make_float4(acc[i][0], acc[i][1], acc[i][2], acc[i][3]);
        *(float4*)&part[((size_t)(slot*NBATCH + n))*G4 + col0] = v;
    }
}

// ---------------- encoder pointwise (4 K-partials per dir) ----------------
__global__ __launch_bounds__(512)
void enc_pointwise_kernel(const float* __restrict__ part,
                          const float* __restrict__ xp0, const float* __restrict__ xp1,
                          const float* __restrict__ cin,
                          float* __restrict__ hout, float* __restrict__ cout,
                          float* __restrict__ es0, float* __restrict__ es1)
{
    const int n = blockIdx.x, dir = blockIdx.y, j = threadIdx.x;
    const float* xp = dir ? xp1 : xp0;
    float g4[4];
    #pragma unroll
    for (int g = 0; g < 4; g++) {
        size_t o = (size_t)n*G4 + g*HDIM + j;
        g4[g] = part[(size_t)(0*2+dir)*NG4 + o] + part[(size_t)(1*2+dir)*NG4 + o]
              + part[(size_t)(2*2+dir)*NG4 + o] + part[(size_t)(3*2+dir)*NG4 + o] + xp[o];
    }
    float ig = 1.f/(1.f+expf(-g4[0]));
    float fg = 1.f/(1.f+expf(-g4[1]));
    float gg = tanhf(g4[2]);
    float og = 1.f/(1.f+expf(-g4[3]));
    float cn = fg * cin[(dir*NBATCH+n)*HDIM + j] + ig*gg;
    float hn = og * tanhf(cn);
    cout[(dir*NBATCH+n)*HDIM + j] = cn;
    hout[(dir*NBATCH+n)*HDIM + j] = hn;
    float* es = dir ? es1 : es0;
    es[(size_t)n*ESDIM + j] = hn;
}

// ---------------- decoder fused: blocks 0-127 gate GEMM (split-K4), 128-191 attention+ctx ----------------
__global__ __launch_bounds__(512)
void dec_gemm_ctx_kernel(const float* __restrict__ hin,
                         const float* __restrict__ W,       // dWhh [2048][512]
                         const float* __restrict__ eW,
                         const float* __restrict__ ebias,
                         float* __restrict__ part)
{
    const int bx = blockIdx.x;
    const int tid = threadIdx.x;

    if (bx < 128) {
        // ---- gate GEMM slice (256 active threads) ----
        __shared__ float hs[16][68];
        __shared__ float ws[16][68];
        const int jt = bx & 31;
        const int kc = bx >> 5;          // 0..3
        const int kbeg = kc * 128;
        const int j0 = jt * 16;

        const int r  = tid >> 2;         // valid for tid<256
        const int kq = tid & 3;
        const int wrow = (r >> 4) * HDIM + j0 + (r & 15);
        const int tx = tid & 15, ty = tid >> 4;

        const float* Aptr = hin + (size_t)r * HDIM + kbeg + kq*4;
        const float* Wptr = W + (size_t)wrow * HDIM + kbeg + kq*4;

        float4 fa = make_float4(0.f,0.f,0.f,0.f);
        float4 fw = make_float4(0.f,0.f,0.f,0.f);
        if (tid < 256) { fa = *(const float4*)Aptr; fw = *(const float4*)Wptr; }

        float acc[4][4] = {};
        const int ktiles = 8;            // 128/16

        for (int t = 0; t < ktiles; t++) {
            if (tid < 256) {
                hs[kq*4+0][r] = fa.x; hs[kq*4+1][r] = fa.y; hs[kq*4+2][r] = fa.z; hs[kq*4+3][r] = fa.w;
                ws[kq*4+0][r] = fw.x; ws[kq*4+1][r] = fw.y; ws[kq*4+2][r] = fw.z; ws[kq*4+3][r] = fw.w;
            }
            __syncthreads();
            if (tid < 256) {
                if (t + 1 < ktiles) {
                    fa = *(const float4*)(Aptr + (t+1)*16);
                    fw = *(const float4*)(Wptr + (t+1)*16);
                }
                #pragma unroll
                for (int kk = 0; kk < 16; kk++) {
                    float4 av = *(const float4*)&hs[kk][ty*4];
                    float4 bv = *(const float4*)&ws[kk][tx*4];
                    acc[0][0] += av.x*bv.x; acc[0][1] += av.x*bv.y; acc[0][2] += av.x*bv.z; acc[0][3] += av.x*bv.w;
                    acc[1][0] += av.y*bv.x; acc[1][1] += av.y*bv.y; acc[1][2] += av.y*bv.z; acc[1][3] += av.y*bv.w;
                    acc[2][0] += av.z*bv.x; acc[2][1] += av.z*bv.y; acc[2][2] += av.z*bv.z; acc[2][3] += av.z*bv.w;
                    acc[3][0] += av.w*bv.x; acc[3][1] += av.w*bv.y; acc[3][2] += av.w*bv.z; acc[3][3] += av.w*bv.w;
                }
            }
            __syncthreads();
        }

        if (tid < 256) {
            const int gate = tx >> 2;
            const int col0 = gate*HDIM + j0 + (tx & 3)*4;
            #pragma unroll
            for (int i = 0; i < 4; i++) {
                int n = ty*4 + i;
                float4 v = make_float4(acc[i][0], acc[i][1], acc[i][2], acc[i][3]);
                *(float4*)&part[((size_t)(kc*NBATCH + n))*G4 + col0] = v;
            }
        }
    } else {
        // ---- attention + ctx for one batch element ----
        __shared__ float red[16];
        __shared__ float earr[SS];
        __shared__ float sc[1];
        const int n = bx - 128;
        const int j = tid;

        float p = hin[n*HDIM + j] * eW[j];
        #pragma unroll
        for (int o = 16; o; o >>= 1) p += __shfl_xor_sync(0xffffffffu, p, o);
        if ((j & 31) == 0) red[j >> 5] = p;
        __syncthreads();
        if (j == 0) { float s = 0.f; for (int i = 0; i < 16; i++) s += red[i]; sc[0] = s; }
        __syncthreads();
        float hdot = sc[0];
        if (j < SS) {
            float e = hdot + g_esproj[j*NBATCH + n] + ebias[0];
            earr[j] = e > 0.f ? e : 0.f;
        }
        __syncthreads();
        if (j == 0) {
            float m = earr[0];
            for (int s = 1; s < SS; s++) m = fmaxf(m, earr[s]);
            float sum = 0.f;
            for (int s = 0; s < SS; s++) { float v = expf(earr[s]-m); earr[s] = v; sum += v; }
            sc[0] = 1.f / sum;
        }
        __syncthreads();
        float inv = sc[0];

        // ctx contribution into partial slot 4: thread covers cols [4j,4j+4)
        float4 a = make_float4(0.f, 0.f, 0.f, 0.f);
        for (int s = 0; s < SS; s++) {
            float w = earr[s];
            float4 v = *(const float4*)(g_esw + ((size_t)(s*NBATCH + n))*G4 + j*4);
            a.x += w*v.x; a.y += w*v.y; a.z += w*v.z; a.w += w*v.w;
        }
        float4 o4 = make_float4(a.x*inv, a.y*inv, a.z*inv, a.w*inv);
        *(float4*)&part[(size_t)(4*NBATCH + n)*G4 + j*4] = o4;
    }
}

// ---------------- decoder pointwise: gates = 4 K-partials + ctx + dxp ----------------
__global__ __launch_bounds__(512)
void dec_pw_kernel(const float* __restrict__ part,
                   const float* __restrict__ dxp,
                   const float* __restrict__ cin,
                   float* __restrict__ hout,
                   float* __restrict__ cout,
                   float* __restrict__ hist)
{
    const int n = blockIdx.x, j = threadIdx.x;
    float g4[4];
    #pragma unroll
    for (int g = 0; g < 4; g++) {
        size_t o = (size_t)n*G4 + g*HDIM + j;
        g4[g] = part[o] + part[(size_t)NG4 + o] + part[(size_t)2*NG4 + o]
              + part[(size_t)3*NG4 + o] + part[(size_t)4*NG4 + o] + dxp[o];
    }
    float ig = 1.f/(1.f+expf(-g4[0]));
    float fg = 1.f/(1.f+expf(-g4[1]));
    float gg = tanhf(g4[2]);
    float og = 1.f/(1.f+expf(-g4[3]));
    float cn = fg * cin[n*HDIM + j] + ig*gg;
    float hn = og * tanhf(cn);
    cout[n*HDIM + j] = cn;
    hout[n*HDIM + j] = hn;
    hist[n*HDIM + j] = hn;
}

// ---------------- attention pre-projection ----------------
__global__ void esproj_kernel(const float* __restrict__ eW){
    int gw = (blockIdx.x*blockDim.x + threadIdx.x) >> 5;
    int lane = threadIdx.x & 31;
    if (gw >= SS*NBATCH) return;
    const float* row = g_es + (size_t)gw*ESDIM;
    const float* We  = eW + HDIM;
    float p = 0.f;
    for (int k = lane; k < ESDIM; k += 32) p += row[k] * We[k];
    #pragma unroll
    for (int o = 16; o; o >>= 1) p += __shfl_xor_sync(0xffffffffu, p, o);
    if (lane == 0) g_esproj[gw] = p;
}

// ---------------- host orchestration ----------------
extern "C" void kernel_launch(void* const* d_in, const int* in_sizes, int n_in,
                              void* d_out, int out_size)
{
    (void)in_sizes; (void)n_in; (void)out_size;
    const int*   src     = (const int*)  d_in[0];
    const int*   tgt     = (const int*)  d_in[1];
    const float* enc_emb = (const float*)d_in[2];
    const float* Wih_f   = (const float*)d_in[3];
    const float* Whh_f   = (const float*)d_in[4];
    const float* b_f     = (const float*)d_in[5];
    const float* Wih_b   = (const float*)d_in[6];
    const float* Whh_b   = (const float*)d_in[7];
    const float* b_b     = (const float*)d_in[8];
    const float* fcW_h   = (const float*)d_in[9];
    const float* fcb_h   = (const float*)d_in[10];
    const float* fcW_c   = (const float*)d_in[11];
    const float* fcb_c   = (const float*)d_in[12];
    const float* dec_emb = (const float*)d_in[13];
    const float* dWih    = (const float*)d_in[14];
    const float* dWhh    = (const float*)d_in[15];
    const float* db      = (const float*)d_in[16];
    const float* eW      = (const float*)d_in[17];
    const float* ebias   = (const float*)d_in[18];
    const float* fcW     = (const float*)d_in[19];
    const float* fcb     = (const float*)d_in[20];
    float* out = (float*)d_out;

    float *p_emb, *p_demb, *p_xpf, *p_xpb, *p_dxp, *p_es, *p_h, *p_c,
          *p_hcat, *p_ccat, *p_dh, *p_dc, *p_esw, *p_hhist, *p_part, *p_zb;
    unsigned short *p_abig, *p_bbig, *p_ea2, *p_da2, *p_wf2, *p_wb2, *p_wd2, *p_es3, *p_wc3;
    cudaGetSymbolAddress((void**)&p_emb,   g_emb_src);
    cudaGetSymbolAddress((void**)&p_demb,  g_demb);
    cudaGetSymbolAddress((void**)&p_xpf,   g_xpf);
    cudaGetSymbolAddress((void**)&p_xpb,   g_xpb);
    cudaGetSymbolAddress((void**)&p_dxp,   g_dxp);
    cudaGetSymbolAddress((void**)&p_es,    g_es);
    cudaGetSymbolAddress((void**)&p_h,     g_h_enc);
    cudaGetSymbolAddress((void**)&p_c,     g_c_enc);
    cudaGetSymbolAddress((void**)&p_hcat,  g_hcat);
    cudaGetSymbolAddress((void**)&p_ccat,  g_ccat);
    cudaGetSymbolAddress((void**)&p_dh,    g_dec_h);
    cudaGetSymbolAddress((void**)&p_dc,    g_dec_c);
    cudaGetSymbolAddress((void**)&p_esw,   g_esw);
    cudaGetSymbolAddress((void**)&p_hhist, g_hhist);
    cudaGetSymbolAddress((void**)&p_part,  g_part);
    cudaGetSymbolAddress((void**)&p_zb,    g_zb);
    cudaGetSymbolAddress((void**)&p_abig,  g_abig);
    cudaGetSymbolAddress((void**)&p_bbig,  g_bbig);
    cudaGetSymbolAddress((void**)&p_ea2,   g_ea2);
    cudaGetSymbolAddress((void**)&p_da2,   g_da2);
    cudaGetSymbolAddress((void**)&p_wf2,   g_wf2);
    cudaGetSymbolAddress((void**)&p_wb2,   g_wb2);
    cudaGetSymbolAddress((void**)&p_wd2,   g_wd2);
    cudaGetSymbolAddress((void**)&p_es3,   g_es3);
    cudaGetSymbolAddress((void**)&p_wc3,   g_wc3);

    // ---- Phase A (launch #4 = gemm_tc for ncu capture) ----
    embed_kernel<<<(SS*NBATCH*EDIM + 255)/256, 256>>>(src, enc_emb, p_emb, SS*NBATCH);   // 1
    convA2_kernel<<<(SS*NBATCH*KP + 255)/256, 256>>>(p_emb, p_ea2, SS*NBATCH);           // 2
    convW2_kernel<<<(G4*KP + 255)/256, 256>>>(Wih_f, p_wf2, EDIM, 0);                    // 3
    gemm_tc_kernel<<<dim3(16, 25), 256>>>(p_ea2, p_wf2, b_f, p_xpf, SS*NBATCH, G4, KBIG2); // 4 (profiled)
    convB_kernel<<<(VTGT*HDIM + 255)/256, 256>>>(fcW);
    embed_kernel<<<(TDEC*NBATCH*EDIM + 255)/256, 256>>>(tgt, dec_emb, p_demb, TDEC*NBATCH);
    convA2_kernel<<<(TDEC*NBATCH*KP + 255)/256, 256>>>(p_demb, p_da2, TDEC*NBATCH);
    convW2_kernel<<<(G4*KP + 255)/256, 256>>>(Wih_b, p_wb2, EDIM, 0);
    convW2_kernel<<<(G4*KP + 255)/256, 256>>>(dWih, p_wd2, 2*HDIM + EDIM, ESDIM);
    gemm_tc_kernel<<<dim3(16, 25), 256>>>(p_ea2, p_wb2, b_b, p_xpb, SS*NBATCH, G4, KBIG2);
    gemm_tc_kernel<<<dim3(16, 25), 256>>>(p_da2, p_wd2, db, p_dxp, TDEC*NBATCH, G4, KBIG2);
    convW3_kernel<<<(G4*ESDIM + 255)/256, 256>>>(dWih, 2*HDIM + EDIM);  // Wih_ctx (K=1024)
    zero_kernel<<<(G4 + 255)/256, 256>>>(p_zb, G4);
    zero_kernel<<<(2*NH + 255)/256, 256>>>(p_h, 2*NH);
    zero_kernel<<<(2*NH + 255)/256, 256>>>(p_c, 2*NH);

    // ---- Phase B: encoder recurrence (launch-based, fused fwd+bwd, split-K4) ----
    for (int s = 0; s < SS; s++) {
        int pin = s & 1, pout = pin ^ 1;
        lstm_gemm_kernel<<<dim3(32, 4, 2), 256>>>(
            p_h + (pin*2+0)*NH, p_h + (pin*2+1)*NH, HDIM,
            Whh_f, Whh_b, HDIM, 128, p_part);
        enc_pointwise_kernel<<<dim3(NBATCH, 2), 512>>>(
            p_part,
            p_xpf + (size_t)s*NG4, p_xpb + (size_t)(SS-1-s)*NG4,
            p_c + pin*2*NH, p_h + pout*2*NH, p_c + pout*2*NH,
            p_es + (size_t)s*NBATCH*ESDIM,
            p_es + (size_t)(SS-1-s)*NBATCH*ESDIM + HDIM);
    }

    // ---- Bridge + attention precomputation ----
    hccat_kernel<<<(NBATCH*ESDIM + 255)/256, 256>>>();
    gemm_kernel<<<dim3(8, 1), 256>>>(p_hcat, ESDIM, fcW_h, ESDIM, fcb_h,
                                     p_dh, HDIM, NBATCH, HDIM, ESDIM);
    gemm_kernel<<<dim3(8, 1), 256>>>(p_ccat, ESDIM, fcW_c, ESDIM, fcb_c,
                                     p_dc, HDIM, NBATCH, HDIM, ESDIM);
    esproj_kernel<<<(SS*NBATCH*32 + 255)/256, 256>>>(eW);
    convES_kernel<<<(SS*NBATCH*ESDIM + 255)/256, 256>>>();
    gemm_tc_kernel<<<dim3(16, 25), 256>>>(p_es3, p_wc3, p_zb, p_esw,
                                          SS*NBATCH, G4, KBIG3);

    // ---- Phase C: decoder recurrence (fused GEMM∥attention+ctx, then pointwise) ----
    for (int t = 0; t < TDEC; t++) {
        int pin = t & 1, pout = pin ^ 1;
        dec_gemm_ctx_kernel<<<192, 512>>>(
            p_dh + pin*NH, dWhh, eW, ebias, p_part);
        dec_pw_kernel<<<NBATCH, 512>>>(
            p_part, p_dxp + (size_t)t*NG4,
            p_dc + pin*NH,
            p_dh + pout*NH, p_dc + pout*NH,
            p_hhist + (size_t)t*NH);
    }

    // ---- Phase D: output — bf16-split tensor-core GEMM ----
    zero_kernel<<<(NBATCH*VTGT + 255)/256, 256>>>(out, NBATCH*VTGT);
    convA_kernel<<<(MOUT*HDIM + 255)/256, 256>>>(p_hhist);
    gemm_tc_kernel<<<dim3((VTGT + 127)/128, (MOUT + 127)/128), 256>>>(
        p_abig, p_bbig, fcb, out + (size_t)NBATCH*VTGT, MOUT, VTGT, KBIG);
}

// round 17
// speedup vs baseline: 1.5472x; 1.0576x over previous
#include <cuda_runtime.h>
#include <math.h>

#define SS      50
#define NBATCH  64
#define EDIM    300
#define HDIM    512
#define G4      2048
#define ESDIM   1024
#define VTGT    10000
#define TDEC    49
#define NH      (NBATCH*HDIM)
#define NG4     (NBATCH*G4)
#define MOUT    (TDEC*NBATCH)
#define KBIG    1536
#define KP      320
#define KBIG2   960
#define KBIG3   3072
#define BST2    40

// ---------------- scratch (device globals; no runtime allocation) ----------------
__device__ float g_emb_src[SS*NBATCH*EDIM];
__device__ float g_demb  [TDEC*NBATCH*EDIM];
__device__ float g_xpf   [SS*NBATCH*G4];
__device__ float g_xpb   [SS*NBATCH*G4];
__device__ float g_dxp   [TDEC*NBATCH*G4];
__device__ float g_es    [SS*NBATCH*ESDIM];
__device__ float g_h_enc [2*2*NBATCH*HDIM];   // [parity][dir][n][h]
__device__ float g_c_enc [2*2*NBATCH*HDIM];
__device__ float g_hcat  [NBATCH*ESDIM];
__device__ float g_ccat  [NBATCH*ESDIM];
__device__ float g_dec_h [2*NBATCH*HDIM];
__device__ float g_dec_c [2*NBATCH*HDIM];
__device__ float g_esproj[SS*NBATCH];
__device__ float g_esw   [SS*NBATCH*G4];      // es[s,n,:]·Wih_ctx^T
__device__ float g_hhist [TDEC*NBATCH*HDIM];
__device__ float g_part  [8*NBATCH*G4];       // slots 0-3: K-partials, slot 4: ctx
__device__ float g_zb    [G4];
__device__ unsigned short g_abig[MOUT*KBIG];      // bf16 bits: [Ah|Ah|Al]
__device__ unsigned short g_bbig[VTGT*KBIG];      // bf16 bits: [Bh|Bl|Bh]
__device__ unsigned short g_ea2 [SS*NBATCH*KBIG2];
__device__ unsigned short g_da2 [TDEC*NBATCH*KBIG2];
__device__ unsigned short g_wf2 [G4*KBIG2];
__device__ unsigned short g_wb2 [G4*KBIG2];
__device__ unsigned short g_wd2 [G4*KBIG2];
__device__ unsigned short g_es3 [SS*NBATCH*KBIG3];
__device__ unsigned short g_wc3 [G4*KBIG3];

// ---------------- bf16 bit helpers (round-to-nearest-even) ----------------
__device__ __forceinline__ unsigned short f2bf(float x){
    unsigned int u = __float_as_uint(x);
    unsigned int r = (u + 0x7fffu + ((u >> 16) & 1u)) >> 16;
    return (unsigned short)r;
}
__device__ __forceinline__ float bf2f(unsigned short b){
    return __uint_as_float(((unsigned int)b) << 16);
}

// ---------------- small utility kernels ----------------
__global__ void zero_kernel(float* __restrict__ p, int n){
    int i = blockIdx.x*blockDim.x + threadIdx.x;
    if (i < n) p[i] = 0.f;
}

__global__ void embed_kernel(const int* __restrict__ tok,
                             const float* __restrict__ table,
                             float* __restrict__ out, int rows){
    int i = blockIdx.x*blockDim.x + threadIdx.x;
    int total = rows * EDIM;
    if (i >= total) return;
    int r = i / EDIM, e = i - r*EDIM;
    out[i] = table[(size_t)tok[r]*EDIM + e];
}

__global__ void hccat_kernel(){
    int i = blockIdx.x*blockDim.x + threadIdx.x;
    if (i >= NBATCH*ESDIM) return;
    int n = i >> 10, k = i & 1023;
    int src = (k < HDIM) ? (0*NH + n*HDIM + k)
                         : (1*NH + n*HDIM + (k - HDIM));
    g_hcat[i] = g_h_enc[src];
    g_ccat[i] = g_c_enc[src];
}

// Phase-D conversions (K=512 splits, KBIG=1536)
__global__ void convA_kernel(const float* __restrict__ X){
    int i = blockIdx.x*blockDim.x + threadIdx.x;
    if (i >= MOUT*HDIM) return;
    int m = i >> 9, k = i & 511;
    float x = X[i];
    unsigned short hi = f2bf(x);
    unsigned short lo = f2bf(x - bf2f(hi));
    g_abig[(size_t)m*KBIG + k]        = hi;
    g_abig[(size_t)m*KBIG + 512 + k]  = hi;
    g_abig[(size_t)m*KBIG + 1024 + k] = lo;
}

__global__ void convB_kernel(const float* __restrict__ W){
    int i = blockIdx.x*blockDim.x + threadIdx.x;
    if (i >= VTGT*HDIM) return;
    int n = i >> 9, k = i & 511;
    float x = W[i];
    unsigned short hi = f2bf(x);
    unsigned short lo = f2bf(x - bf2f(hi));
    g_bbig[(size_t)n*KBIG + k]        = hi;
    g_bbig[(size_t)n*KBIG + 512 + k]  = lo;
    g_bbig[(size_t)n*KBIG + 1024 + k] = hi;
}

// Phase-A conversions (K=300 padded to 320, KBIG2=960)
__global__ void convA2_kernel(const float* __restrict__ X,
                              unsigned short* __restrict__ dst, int rows){
    int i = blockIdx.x*blockDim.x + threadIdx.x;
    if (i >= rows*KP) return;
    int m = i / KP, k = i - m*KP;
    unsigned short hi = 0, lo = 0;
    if (k < EDIM){
        float x = X[(size_t)m*EDIM + k];
        hi = f2bf(x);
        lo = f2bf(x - bf2f(hi));
    }
    dst[(size_t)m*KBIG2 + k]        = hi;
    dst[(size_t)m*KBIG2 + KP + k]   = hi;
    dst[(size_t)m*KBIG2 + 2*KP + k] = lo;
}

__global__ void convW2_kernel(const float* __restrict__ W,
                              unsigned short* __restrict__ dst, int ldw, int koff){
    int i = blockIdx.x*blockDim.x + threadIdx.x;
    if (i >= G4*KP) return;
    int n = i / KP, k = i - n*KP;
    unsigned short hi = 0, lo = 0;
    if (k < EDIM){
        float x = W[(size_t)n*ldw + koff + k];
        hi = f2bf(x);
        lo = f2bf(x - bf2f(hi));
    }
    dst[(size_t)n*KBIG2 + k]        = hi;
    dst[(size_t)n*KBIG2 + KP + k]   = lo;
    dst[(size_t)n*KBIG2 + 2*KP + k] = hi;
}

// esW conversions (K=1024, KBIG3=3072)
__global__ void convES_kernel(){
    int i = blockIdx.x*blockDim.x + threadIdx.x;
    if (i >= SS*NBATCH*ESDIM) return;
    int m = i >> 10, k = i & 1023;
    float x = g_es[i];
    unsigned short hi = f2bf(x);
    unsigned short lo = f2bf(x - bf2f(hi));
    g_es3[(size_t)m*KBIG3 + k]        = hi;
    g_es3[(size_t)m*KBIG3 + 1024 + k] = hi;
    g_es3[(size_t)m*KBIG3 + 2048 + k] = lo;
}

__global__ void convW3_kernel(const float* __restrict__ W, int ldw){
    int i = blockIdx.x*blockDim.x + threadIdx.x;
    if (i >= G4*ESDIM) return;
    int n = i >> 10, k = i & 1023;
    float x = W[(size_t)n*ldw + k];
    unsigned short hi = f2bf(x);
    unsigned short lo = f2bf(x - bf2f(hi));
    g_wc3[(size_t)n*KBIG3 + k]        = hi;
    g_wc3[(size_t)n*KBIG3 + 1024 + k] = lo;
    g_wc3[(size_t)n*KBIG3 + 2048 + k] = hi;
}

// ---------------- small fp32 GEMM (bridge only): C[M,N] = A*B^T + bias ----------------
__global__ __launch_bounds__(256)
void gemm_kernel(const float* __restrict__ A, int lda,
                 const float* __restrict__ B, int ldb,
                 const float* __restrict__ bias,
                 float* __restrict__ C, int ldc,
                 int M, int N, int K)
{
    __shared__ float As[8][68];
    __shared__ float Bs[8][68];
    const int tid = threadIdx.x;
    const int tx = tid & 15, ty = tid >> 4;
    const int mb = blockIdx.y * 64, nb = blockIdx.x * 64;
    float acc[4][4] = {};

    for (int k0 = 0; k0 < K; k0 += 8) {
        #pragma unroll
        for (int i = 0; i < 2; i++) {
            int idx = tid + i*256;
            int kk = idx & 7, rr = idx >> 3;
            int m = mb + rr, k = k0 + kk;
            As[kk][rr] = (m < M && k < K) ? A[(size_t)m*lda + k] : 0.f;
            int nn = nb + rr;
            Bs[kk][rr] = (nn < N && k < K) ? B[(size_t)nn*ldb + k] : 0.f;
        }
        __syncthreads();
        #pragma unroll
        for (int kk = 0; kk < 8; kk++) {
            float a0 = As[kk][ty*4+0], a1 = As[kk][ty*4+1];
            float a2 = As[kk][ty*4+2], a3 = As[kk][ty*4+3];
            float b0 = Bs[kk][tx*4+0], b1 = Bs[kk][tx*4+1];
            float b2 = Bs[kk][tx*4+2], b3 = Bs[kk][tx*4+3];
            acc[0][0] += a0*b0; acc[0][1] += a0*b1; acc[0][2] += a0*b2; acc[0][3] += a0*b3;
            acc[1][0] += a1*b0; acc[1][1] += a1*b1; acc[1][2] += a1*b2; acc[1][3] += a1*b3;
            acc[2][0] += a2*b0; acc[2][1] += a2*b1; acc[2][2] += a2*b2; acc[2][3] += a2*b3;
            acc[3][0] += a3*b0; acc[3][1] += a3*b1; acc[3][2] += a3*b2; acc[3][3] += a3*b3;
        }
        __syncthreads();
    }
    #pragma unroll
    for (int i = 0; i < 4; i++) {
        int m = mb + ty*4 + i;
        if (m >= M) continue;
        #pragma unroll
        for (int j = 0; j < 4; j++) {
            int nn = nb + tx*4 + j;
            if (nn >= N) continue;
            C[(size_t)m*ldc + nn] = acc[i][j] + (bias ? bias[nn] : 0.f);
        }
    }
}

// ---------------- tensor-core bf16-split GEMM: 32-wide K stages, early loads ----------------
__device__ __forceinline__ void ldsm_x4(unsigned int* r, unsigned int addr){
    asm volatile("ldmatrix.sync.aligned.m8n8.x4.shared.b16 {%0,%1,%2,%3}, [%4];"
        : "=r"(r[0]), "=r"(r[1]), "=r"(r[2]), "=r"(r[3]) : "r"(addr));
}
__device__ __forceinline__ void mma16816(float* c, const unsigned int* a, const unsigned int* b){
    asm volatile("mma.sync.aligned.m16n8k16.row.col.f32.bf16.bf16.f32 "
        "{%0,%1,%2,%3}, {%4,%5,%6,%7}, {%8,%9}, {%0,%1,%2,%3};"
        : "+f"(c[0]), "+f"(c[1]), "+f"(c[2]), "+f"(c[3])
        : "r"(a[0]), "r"(a[1]), "r"(a[2]), "r"(a[3]), "r"(b[0]), "r"(b[1]));
}

__global__ __launch_bounds__(256)
void gemm_tc_kernel(const unsigned short* __restrict__ A,
                    const unsigned short* __restrict__ B,
                    const float* __restrict__ bias,
                    float* __restrict__ C, int M, int N, int K)
{
    __shared__ __align__(16) unsigned short As[2*128*BST2];
    __shared__ __align__(16) unsigned short Bs[2*128*BST2];
    const int tid  = threadIdx.x;
    const int mb   = blockIdx.y * 128;
    const int nb   = blockIdx.x * 128;
    const int warp = tid >> 5;
    const int lane = tid & 31;
    const int wm   = warp & 1;        // 2x4 warp grid; warp tile 64x32
    const int wn   = warp >> 1;

    const int lrow = tid >> 1;        // 0..127
    const int lks  = (tid & 1) * 16;  // shorts offset within 32-wide K stage

    const int arow = (mb + lrow < M);
    const int brow = (nb + lrow < N);
    const unsigned short* aptr = A + (size_t)(arow ? (mb + lrow) : 0)*K + lks;
    const unsigned short* bptr = B + (size_t)(brow ? (nb + lrow) : 0)*K + lks;

    // stage 0
    {
        float4 a0 = make_float4(0.f,0.f,0.f,0.f), a1 = a0, b0 = a0, b1 = a0;
        if (arow) { a0 = *(const float4*)(aptr); a1 = *(const float4*)(aptr + 8); }
        if (brow) { b0 = *(const float4*)(bptr); b1 = *(const float4*)(bptr + 8); }
        *(float4*)&As[lrow*BST2 + lks]     = a0;
        *(float4*)&As[lrow*BST2 + lks + 8] = a1;
        *(float4*)&Bs[lrow*BST2 + lks]     = b0;
        *(float4*)&Bs[lrow*BST2 + lks + 8] = b1;
    }
    __syncthreads();

    float acc[4][4][4];
    #pragma unroll
    for (int i = 0; i < 4; i++)
        #pragma unroll
        for (int j = 0; j < 4; j++) {
            acc[i][j][0] = 0.f; acc[i][j][1] = 0.f;
            acc[i][j][2] = 0.f; acc[i][j][3] = 0.f;
        }

    const int fr  = (lane & 7) + ((lane >> 3) & 1) * 8;   // A: row within 16
    const int fcA = ((lane >> 4) & 1) * 8;                // A: k-half
    const int frB = (lane & 7) + ((lane >> 4) & 1) * 8;   // B: n row within 16
    const int fcB = ((lane >> 3) & 1) * 8;                // B: k-half

    const unsigned int a_base = (unsigned int)__cvta_generic_to_shared(&As[0]);
    const unsigned int b_base = (unsigned int)__cvta_generic_to_shared(&Bs[0]);
    const unsigned int stage_bytes = 128u * BST2 * 2u;

    const int NT = K / 32;
    for (int t = 0; t < NT; t++) {
        const int buf = t & 1;
        const unsigned int ab = a_base + (unsigned int)buf * stage_bytes;
        const unsigned int bb = b_base + (unsigned int)buf * stage_bytes;

        // ---- EARLY global loads for the next stage (latency hidden by MMAs below) ----
        float4 na0, na1, nb0, nb1;
        na0 = make_float4(0.f,0.f,0.f,0.f); na1 = na0; nb0 = na0; nb1 = na0;
        if (t + 1 < NT) {
            const int k0 = (t + 1) * 32;
            if (arow) { na0 = *(const float4*)(aptr + k0); na1 = *(const float4*)(aptr + k0 + 8); }
            if (brow) { nb0 = *(const float4*)(bptr + k0); nb1 = *(const float4*)(bptr + k0 + 8); }
        }

        // ---- k-half 0 ----
        {
            unsigned int areg[4][4];
            unsigned int breg[4][2];
            #pragma unroll
            for (int i = 0; i < 4; i++) {
                int row = wm*64 + i*16 + fr;
                ldsm_x4(areg[i], ab + (unsigned int)(row*BST2 + fcA) * 2u);
            }
            #pragma unroll
            for (int p = 0; p < 2; p++) {
                int row = wn*32 + p*16 + frB;
                unsigned int r4[4];
                ldsm_x4(r4, bb + (unsigned int)(row*BST2 + fcB) * 2u);
                breg[p*2][0]   = r4[0];
                breg[p*2][1]   = r4[1];
                breg[p*2+1][0] = r4[2];
                breg[p*2+1][1] = r4[3];
            }
            #pragma unroll
            for (int i = 0; i < 4; i++)
                #pragma unroll
                for (int j = 0; j < 4; j++)
                    mma16816(acc[i][j], areg[i], breg[j]);
        }

        // ---- k-half 1 ----
        {
            unsigned int areg[4][4];
            unsigned int breg[4][2];
            #pragma unroll
            for (int i = 0; i < 4; i++) {
                int row = wm*64 + i*16 + fr;
                ldsm_x4(areg[i], ab + (unsigned int)(row*BST2 + 16 + fcA) * 2u);
            }
            #pragma unroll
            for (int p = 0; p < 2; p++) {
                int row = wn*32 + p*16 + frB;
                unsigned int r4[4];
                ldsm_x4(r4, bb + (unsigned int)(row*BST2 + 16 + fcB) * 2u);
                breg[p*2][0]   = r4[0];
                breg[p*2][1]   = r4[1];
                breg[p*2+1][0] = r4[2];
                breg[p*2+1][1] = r4[3];
            }
            #pragma unroll
            for (int i = 0; i < 4; i++)
                #pragma unroll
                for (int j = 0; j < 4; j++)
                    mma16816(acc[i][j], areg[i], breg[j]);
        }

        // ---- LATE smem stores for next stage ----
        if (t + 1 < NT) {
            const int nbuf = buf ^ 1;
            *(float4*)&As[nbuf*128*BST2 + lrow*BST2 + lks]     = na0;
            *(float4*)&As[nbuf*128*BST2 + lrow*BST2 + lks + 8] = na1;
            *(float4*)&Bs[nbuf*128*BST2 + lrow*BST2 + lks]     = nb0;
            *(float4*)&Bs[nbuf*128*BST2 + lrow*BST2 + lks + 8] = nb1;
        }
        __syncthreads();
    }

    const int er = lane >> 2;
    const int ec = (lane & 3) * 2;
    #pragma unroll
    for (int i = 0; i < 4; i++) {
        #pragma unroll
        for (int j = 0; j < 4; j++) {
            int m0 = mb + wm*64 + i*16 + er;
            int n0 = nb + wn*32 + j*8 + ec;
            if (n0 < N) {
                if (m0 < M) {
                    C[(size_t)m0*N + n0] = acc[i][j][0] + bias[n0];
                    if (n0+1 < N) C[(size_t)m0*N + n0+1] = acc[i][j][1] + bias[n0+1];
                }
                if (m0+8 < M) {
                    C[(size_t)(m0+8)*N + n0] = acc[i][j][2] + bias[n0];
                    if (n0+1 < N) C[(size_t)(m0+8)*N + n0+1] = acc[i][j][3] + bias[n0+1];
                }
            }
        }
    }
}

// ---------------- LSTM gate GEMM (split-K, dual input): partial[slot][n][2048] ----------------
__global__ __launch_bounds__(256)
void lstm_gemm_kernel(const float* __restrict__ A0, const float* __restrict__ A1, int lda,
                      const float* __restrict__ W0, const float* __restrict__ W1, int ldw,
                      int kchunk, float* __restrict__ part)
{
    __shared__ float hs[16][68];
    __shared__ float ws[16][68];
    const int tid = threadIdx.x;
    const int dir = blockIdx.z;
    const int slot = blockIdx.y * gridDim.z + blockIdx.z;
    const float* __restrict__ A = dir ? A1 : A0;
    const float* __restrict__ W = dir ? W1 : W0;
    const int kbeg = blockIdx.y * kchunk;
    const int j0 = blockIdx.x * 16;

    const int r  = tid >> 2;
    const int kq = tid & 3;
    const int wrow = (r >> 4) * HDIM + j0 + (r & 15);
    const int tx = tid & 15, ty = tid >> 4;

    const float* Aptr = A + (size_t)r * lda + kbeg + kq*4;
    const float* Wptr = W + (size_t)wrow * ldw + kbeg + kq*4;

    float4 fa = *(const float4*)Aptr;
    float4 fw = *(const float4*)Wptr;

    float acc[4][4] = {};
    const int ktiles = kchunk / 16;

    for (int t = 0; t < ktiles; t++) {
        hs[kq*4+0][r] = fa.x; hs[kq*4+1][r] = fa.y; hs[kq*4+2][r] = fa.z; hs[kq*4+3][r] = fa.w;
        ws[kq*4+0][r] = fw.x; ws[kq*4+1][r] = fw.y; ws[kq*4+2][r] = fw.z; ws[kq*4+3][r] = fw.w;
        __syncthreads();
        if (t + 1 < ktiles) {
            fa = *(const float4*)(Aptr + (t+1)*16);
            fw = *(const float4*)(Wptr + (t+1)*16);
        }
        #pragma unroll
        for (int kk = 0; kk < 16; kk++) {
            float4 av = *(const float4*)&hs[kk][ty*4];
            float4 bv = *(const float4*)&ws[kk][tx*4];
            acc[0][0] += av.x*bv.x; acc[0][1] += av.x*bv.y; acc[0][2] += av.x*bv.z; acc[0][3] += av.x*bv.w;
            acc[1][0] += av.y*bv.x; acc[1][1] += av.y*bv.y; acc[1][2] += av.y*bv.z; acc[1][3] += av.y*bv.w;
            acc[2][0] += av.z*bv.x; acc[2][1] += av.z*bv.y; acc[2][2] += av.z*bv.z; acc[2][3] += av.z*bv.w;
            acc[3][0] += av.w*bv.x; acc[3][1] += av.w*bv.y; acc[3][2] += av.w*bv.z; acc[3][3] += av.w*bv.w;
        }
        __syncthreads();
    }

    const int gate = tx >> 2;
    const int col0 = gate*HDIM + j0 + (tx & 3)*4;
    #pragma unroll
    for (int i = 0; i < 4; i++) {
        int n = ty*4 + i;
        float4 v = make_float4(acc[i][0], acc[i][1], acc[i][2], acc[i][3]);
        *(float4*)&part[((size_t)(slot*NBATCH + n))*G4 + col0] = v;
    }
}

// ---------------- encoder pointwise (4 K-partials per dir) ----------------
__global__ __launch_bounds__(512)
void enc_pointwise_kernel(const float* __restrict__ part,
                          const float* __restrict__ xp0, const float* __restrict__ xp1,
                          const float* __restrict__ cin,
                          float* __restrict__ hout, float* __restrict__ cout,
                          float* __restrict__ es0, float* __restrict__ es1)
{
    const int n = blockIdx.x, dir = blockIdx.y, j = threadIdx.x;
    const float* xp = dir ? xp1 : xp0;
    float g4[4];
    #pragma unroll
    for (int g = 0; g < 4; g++) {
        size_t o = (size_t)n*G4 + g*HDIM + j;
        g4[g] = part[(size_t)(0*2+dir)*NG4 + o] + part[(size_t)(1*2+dir)*NG4 + o]
              + part[(size_t)(2*2+dir)*NG4 + o] + part[(size_t)(3*2+dir)*NG4 + o] + xp[o];
    }
    float ig = 1.f/(1.f+expf(-g4[0]));
    float fg = 1.f/(1.f+expf(-g4[1]));
    float gg = tanhf(g4[2]);
    float og = 1.f/(1.f+expf(-g4[3]));
    float cn = fg * cin[(dir*NBATCH+n)*HDIM + j] + ig*gg;
    float hn = og * tanhf(cn);
    cout[(dir*NBATCH+n)*HDIM + j] = cn;
    hout[(dir*NBATCH+n)*HDIM + j] = hn;
    float* es = dir ? es1 : es0;
    es[(size_t)n*ESDIM + j] = hn;
}

// ---------------- decoder fused: blocks 0-127 gate GEMM (split-K4), 128-191 attention+ctx ----------------
__global__ __launch_bounds__(512)
void dec_gemm_ctx_kernel(const float* __restrict__ hin,
                         const float* __restrict__ W,       // dWhh [2048][512]
                         const float* __restrict__ eW,
                         const float* __restrict__ ebias,
                         float* __restrict__ part)
{
    const int bx = blockIdx.x;
    const int tid = threadIdx.x;

    if (bx < 128) {
        __shared__ float hs[16][68];
        __shared__ float ws[16][68];
        const int jt = bx & 31;
        const int kc = bx >> 5;
        const int kbeg = kc * 128;
        const int j0 = jt * 16;

        const int r  = tid >> 2;
        const int kq = tid & 3;
        const int wrow = (r >> 4) * HDIM + j0 + (r & 15);
        const int tx = tid & 15, ty = tid >> 4;

        const float* Aptr = hin + (size_t)r * HDIM + kbeg + kq*4;
        const float* Wptr = W + (size_t)wrow * HDIM + kbeg + kq*4;

        float4 fa = make_float4(0.f,0.f,0.f,0.f);
        float4 fw = make_float4(0.f,0.f,0.f,0.f);
        if (tid < 256) { fa = *(const float4*)Aptr; fw = *(const float4*)Wptr; }

        float acc[4][4] = {};
        const int ktiles = 8;

        for (int t = 0; t < ktiles; t++) {
            if (tid < 256) {
                hs[kq*4+0][r] = fa.x; hs[kq*4+1][r] = fa.y; hs[kq*4+2][r] = fa.z; hs[kq*4+3][r] = fa.w;
                ws[kq*4+0][r] = fw.x; ws[kq*4+1][r] = fw.y; ws[kq*4+2][r] = fw.z; ws[kq*4+3][r] = fw.w;
            }
            __syncthreads();
            if (tid < 256) {
                if (t + 1 < ktiles) {
                    fa = *(const float4*)(Aptr + (t+1)*16);
                    fw = *(const float4*)(Wptr + (t+1)*16);
                }
                #pragma unroll
                for (int kk = 0; kk < 16; kk++) {
                    float4 av = *(const float4*)&hs[kk][ty*4];
                    float4 bv = *(const float4*)&ws[kk][tx*4];
                    acc[0][0] += av.x*bv.x; acc[0][1] += av.x*bv.y; acc[0][2] += av.x*bv.z; acc[0][3] += av.x*bv.w;
                    acc[1][0] += av.y*bv.x; acc[1][1] += av.y*bv.y; acc[1][2] += av.y*bv.z; acc[1][3] += av.y*bv.w;
                    acc[2][0] += av.z*bv.x; acc[2][1] += av.z*bv.y; acc[2][2] += av.z*bv.z; acc[2][3] += av.z*bv.w;
                    acc[3][0] += av.w*bv.x; acc[3][1] += av.w*bv.y; acc[3][2] += av.w*bv.z; acc[3][3] += av.w*bv.w;
                }
            }
            __syncthreads();
        }

        if (tid < 256) {
            const int gate = tx >> 2;
            const int col0 = gate*HDIM + j0 + (tx & 3)*4;
            #pragma unroll
            for (int i = 0; i < 4; i++) {
                int n = ty*4 + i;
                float4 v = make_float4(acc[i][0], acc[i][1], acc[i][2], acc[i][3]);
                *(float4*)&part[((size_t)(kc*NBATCH + n))*G4 + col0] = v;
            }
        }
    } else {
        __shared__ float red[16];
        __shared__ float earr[SS];
        __shared__ float sc[1];
        const int n = bx - 128;
        const int j = tid;

        float p = hin[n*HDIM + j] * eW[j];
        #pragma unroll
        for (int o = 16; o; o >>= 1) p += __shfl_xor_sync(0xffffffffu, p, o);
        if ((j & 31) == 0) red[j >> 5] = p;
        __syncthreads();
        if (j == 0) { float s = 0.f; for (int i = 0; i < 16; i++) s += red[i]; sc[0] = s; }
        __syncthreads();
        float hdot = sc[0];
        if (j < SS) {
            float e = hdot + g_esproj[j*NBATCH + n] + ebias[0];
            earr[j] = e > 0.f ? e : 0.f;
        }
        __syncthreads();
        if (j == 0) {
            float m = earr[0];
            for (int s = 1; s < SS; s++) m = fmaxf(m, earr[s]);
            float sum = 0.f;
            for (int s = 0; s < SS; s++) { float v = expf(earr[s]-m); earr[s] = v; sum += v; }
            sc[0] = 1.f / sum;
        }
        __syncthreads();
        float inv = sc[0];

        float4 a = make_float4(0.f, 0.f, 0.f, 0.f);
        for (int s = 0; s < SS; s++) {
            float w = earr[s];
            float4 v = *(const float4*)(g_esw + ((size_t)(s*NBATCH + n))*G4 + j*4);
            a.x += w*v.x; a.y += w*v.y; a.z += w*v.z; a.w += w*v.w;
        }
        float4 o4 = make_float4(a.x*inv, a.y*inv, a.z*inv, a.w*inv);
        *(float4*)&part[(size_t)(4*NBATCH + n)*G4 + j*4] = o4;
    }
}

// ---------------- decoder pointwise: gates = 4 K-partials + ctx + dxp ----------------
__global__ __launch_bounds__(512)
void dec_pw_kernel(const float* __restrict__ part,
                   const float* __restrict__ dxp,
                   const float* __restrict__ cin,
                   float* __restrict__ hout,
                   float* __restrict__ cout,
                   float* __restrict__ hist)
{
    const int n = blockIdx.x, j = threadIdx.x;
    float g4[4];
    #pragma unroll
    for (int g = 0; g < 4; g++) {
        size_t o = (size_t)n*G4 + g*HDIM + j;
        g4[g] = part[o] + part[(size_t)NG4 + o] + part[(size_t)2*NG4 + o]
              + part[(size_t)3*NG4 + o] + part[(size_t)4*NG4 + o] + dxp[o];
    }
    float ig = 1.f/(1.f+expf(-g4[0]));
    float fg = 1.f/(1.f+expf(-g4[1]));
    float gg = tanhf(g4[2]);
    float og = 1.f/(1.f+expf(-g4[3]));
    float cn = fg * cin[n*HDIM + j] + ig*gg;
    float hn = og * tanhf(cn);
    cout[n*HDIM + j] = cn;
    hout[n*HDIM + j] = hn;
    hist[n*HDIM + j] = hn;
}

// ---------------- attention pre-projection ----------------
__global__ void esproj_kernel(const float* __restrict__ eW){
    int gw = (blockIdx.x*blockDim.x + threadIdx.x) >> 5;
    int lane = threadIdx.x & 31;
    if (gw >= SS*NBATCH) return;
    const float* row = g_es + (size_t)gw*ESDIM;
    const float* We  = eW + HDIM;
    float p = 0.f;
    for (int k = lane; k < ESDIM; k += 32) p += row[k] * We[k];
    #pragma unroll
    for (int o = 16; o; o >>= 1) p += __shfl_xor_sync(0xffffffffu, p, o);
    if (lane == 0) g_esproj[gw] = p;
}

// ---------------- host orchestration ----------------
extern "C" void kernel_launch(void* const* d_in, const int* in_sizes, int n_in,
                              void* d_out, int out_size)
{
    (void)in_sizes; (void)n_in; (void)out_size;
    const int*   src     = (const int*)  d_in[0];
    const int*   tgt     = (const int*)  d_in[1];
    const float* enc_emb = (const float*)d_in[2];
    const float* Wih_f   = (const float*)d_in[3];
    const float* Whh_f   = (const float*)d_in[4];
    const float* b_f     = (const float*)d_in[5];
    const float* Wih_b   = (const float*)d_in[6];
    const float* Whh_b   = (const float*)d_in[7];
    const float* b_b     = (const float*)d_in[8];
    const float* fcW_h   = (const float*)d_in[9];
    const float* fcb_h   = (const float*)d_in[10];
    const float* fcW_c   = (const float*)d_in[11];
    const float* fcb_c   = (const float*)d_in[12];
    const float* dec_emb = (const float*)d_in[13];
    const float* dWih    = (const float*)d_in[14];
    const float* dWhh    = (const float*)d_in[15];
    const float* db      = (const float*)d_in[16];
    const float* eW      = (const float*)d_in[17];
    const float* ebias   = (const float*)d_in[18];
    const float* fcW     = (const float*)d_in[19];
    const float* fcb     = (const float*)d_in[20];
    float* out = (float*)d_out;

    float *p_emb, *p_demb, *p_xpf, *p_xpb, *p_dxp, *p_es, *p_h, *p_c,
          *p_hcat, *p_ccat, *p_dh, *p_dc, *p_esw, *p_hhist, *p_part, *p_zb;
    unsigned short *p_abig, *p_bbig, *p_ea2, *p_da2, *p_wf2, *p_wb2, *p_wd2, *p_es3, *p_wc3;
    cudaGetSymbolAddress((void**)&p_emb,   g_emb_src);
    cudaGetSymbolAddress((void**)&p_demb,  g_demb);
    cudaGetSymbolAddress((void**)&p_xpf,   g_xpf);
    cudaGetSymbolAddress((void**)&p_xpb,   g_xpb);
    cudaGetSymbolAddress((void**)&p_dxp,   g_dxp);
    cudaGetSymbolAddress((void**)&p_es,    g_es);
    cudaGetSymbolAddress((void**)&p_h,     g_h_enc);
    cudaGetSymbolAddress((void**)&p_c,     g_c_enc);
    cudaGetSymbolAddress((void**)&p_hcat,  g_hcat);
    cudaGetSymbolAddress((void**)&p_ccat,  g_ccat);
    cudaGetSymbolAddress((void**)&p_dh,    g_dec_h);
    cudaGetSymbolAddress((void**)&p_dc,    g_dec_c);
    cudaGetSymbolAddress((void**)&p_esw,   g_esw);
    cudaGetSymbolAddress((void**)&p_hhist, g_hhist);
    cudaGetSymbolAddress((void**)&p_part,  g_part);
    cudaGetSymbolAddress((void**)&p_zb,    g_zb);
    cudaGetSymbolAddress((void**)&p_abig,  g_abig);
    cudaGetSymbolAddress((void**)&p_bbig,  g_bbig);
    cudaGetSymbolAddress((void**)&p_ea2,   g_ea2);
    cudaGetSymbolAddress((void**)&p_da2,   g_da2);
    cudaGetSymbolAddress((void**)&p_wf2,   g_wf2);
    cudaGetSymbolAddress((void**)&p_wb2,   g_wb2);
    cudaGetSymbolAddress((void**)&p_wd2,   g_wd2);
    cudaGetSymbolAddress((void**)&p_es3,   g_es3);
    cudaGetSymbolAddress((void**)&p_wc3,   g_wc3);

    // ---- Phase A (launch #4 = gemm_tc for ncu capture) ----
    embed_kernel<<<(SS*NBATCH*EDIM + 255)/256, 256>>>(src, enc_emb, p_emb, SS*NBATCH);
    convA2_kernel<<<(SS*NBATCH*KP + 255)/256, 256>>>(p_emb, p_ea2, SS*NBATCH);
    convW2_kernel<<<(G4*KP + 255)/256, 256>>>(Wih_f, p_wf2, EDIM, 0);
    gemm_tc_kernel<<<dim3(16, 25), 256>>>(p_ea2, p_wf2, b_f, p_xpf, SS*NBATCH, G4, KBIG2);
    convB_kernel<<<(VTGT*HDIM + 255)/256, 256>>>(fcW);
    embed_kernel<<<(TDEC*NBATCH*EDIM + 255)/256, 256>>>(tgt, dec_emb, p_demb, TDEC*NBATCH);
    convA2_kernel<<<(TDEC*NBATCH*KP + 255)/256, 256>>>(p_demb, p_da2, TDEC*NBATCH);
    convW2_kernel<<<(G4*KP + 255)/256, 256>>>(Wih_b, p_wb2, EDIM, 0);
    convW2_kernel<<<(G4*KP + 255)/256, 256>>>(dWih, p_wd2, 2*HDIM + EDIM, ESDIM);
    gemm_tc_kernel<<<dim3(16, 25), 256>>>(p_ea2, p_wb2, b_b, p_xpb, SS*NBATCH, G4, KBIG2);
    gemm_tc_kernel<<<dim3(16, 25), 256>>>(p_da2, p_wd2, db, p_dxp, TDEC*NBATCH, G4, KBIG2);
    convW3_kernel<<<(G4*ESDIM + 255)/256, 256>>>(dWih, 2*HDIM + EDIM);  // Wih_ctx (K=1024)
    zero_kernel<<<(G4 + 255)/256, 256>>>(p_zb, G4);
    zero_kernel<<<(2*NH + 255)/256, 256>>>(p_h, 2*NH);
    zero_kernel<<<(2*NH + 255)/256, 256>>>(p_c, 2*NH);

    // ---- Phase B: encoder recurrence (launch-based, fused fwd+bwd, split-K4) ----
    for (int s = 0; s < SS; s++) {
        int pin = s & 1, pout = pin ^ 1;
        lstm_gemm_kernel<<<dim3(32, 4, 2), 256>>>(
            p_h + (pin*2+0)*NH, p_h + (pin*2+1)*NH, HDIM,
            Whh_f, Whh_b, HDIM, 128, p_part);
        enc_pointwise_kernel<<<dim3(NBATCH, 2), 512>>>(
            p_part,
            p_xpf + (size_t)s*NG4, p_xpb + (size_t)(SS-1-s)*NG4,
            p_c + pin*2*NH, p_h + pout*2*NH, p_c + pout*2*NH,
            p_es + (size_t)s*NBATCH*ESDIM,
            p_es + (size_t)(SS-1-s)*NBATCH*ESDIM + HDIM);
    }

    // ---- Bridge + attention precomputation ----
    hccat_kernel<<<(NBATCH*ESDIM + 255)/256, 256>>>();
    gemm_kernel<<<dim3(8, 1), 256>>>(p_hcat, ESDIM, fcW_h, ESDIM, fcb_h,
                                     p_dh, HDIM, NBATCH, HDIM, ESDIM);
    gemm_kernel<<<dim3(8, 1), 256>>>(p_ccat, ESDIM, fcW_c, ESDIM, fcb_c,
                                     p_dc, HDIM, NBATCH, HDIM, ESDIM);
    esproj_kernel<<<(SS*NBATCH*32 + 255)/256, 256>>>(eW);
    convES_kernel<<<(SS*NBATCH*ESDIM + 255)/256, 256>>>();
    gemm_tc_kernel<<<dim3(16, 25), 256>>>(p_es3, p_wc3, p_zb, p_esw,
                                          SS*NBATCH, G4, KBIG3);

    // ---- Phase C: decoder recurrence (fused GEMM∥attention+ctx, then pointwise) ----
    for (int t = 0; t < TDEC; t++) {
        int pin = t & 1, pout = pin ^ 1;
        dec_gemm_ctx_kernel<<<192, 512>>>(
            p_dh + pin*NH, dWhh, eW, ebias, p_part);
        dec_pw_kernel<<<NBATCH, 512>>>(
            p_part, p_dxp + (size_t)t*NG4,
            p_dc + pin*NH,
            p_dh + pout*NH, p_dc + pout*NH,
            p_hhist + (size_t)t*NH);
    }

    // ---- Phase D: output — bf16-split tensor-core GEMM ----
    zero_kernel<<<(NBATCH*VTGT + 255)/256, 256>>>(out, NBATCH*VTGT);
    convA_kernel<<<(MOUT*HDIM + 255)/256, 256>>>(p_hhist);
    gemm_tc_kernel<<<dim3((VTGT + 127)/128, (MOUT + 127)/128), 256>>>(
        p_abig, p_bbig, fcb, out + (size_t)NBATCH*VTGT, MOUT, VTGT, KBIG);
}